// round 3
// baseline (speedup 1.0000x reference)
#include <cuda_runtime.h>
#include <math.h>

#define B_ 2
#define T_ 1024
#define D_ 1024
#define H_ 16
#define HKV_ 8
#define HD_ 64
#define NL_ 3
#define MAXKV_ 3072
#define MT_ 2048            // B*T rows
#define EPS_ 1e-5f
#define SMS 68              // padded smem stride (float4-aligned: 68*4 = 272 = 17*16)
#define ATTN_SMEM (4 * 64 * SMS * (int)sizeof(float))

// ---------------- scratch (device globals; no allocations allowed) ----------------
__device__ __align__(256) float g_q[NL_ * MT_ * D_];        // q projections, roped in place
__device__ __align__(256) float g_k[NL_ * MT_ * (D_ / 2)];  // k staging (pre-rope)
__device__ __align__(256) float g_v[NL_ * MT_ * (D_ / 2)];  // v staging
__device__ __align__(256) float g_Kc[B_ * HKV_ * MAXKV_ * HD_]; // rotated K cache [b][hkv][pos][d]
__device__ __align__(256) float g_Vc[B_ * HKV_ * MAXKV_ * HD_]; // V cache
__device__ __align__(256) float g_o[NL_ * MT_ * D_];        // attention outputs per layer
__device__ __align__(256) float g_y[MT_ * D_];              // pre-output-proj activations
__device__ float g_lw[NL_];

// ---------------- lambda-weight prep ----------------
__global__ void k_prep(const float* __restrict__ lam) {
    if (threadIdx.x == 0) {
        float s0 = 1.f / (1.f + expf(-lam[0]));
        float s1 = 1.f / (1.f + expf(-lam[1]));
        float s2 = 1.f / (1.f + expf(-lam[2]));
        float mean = (s0 + s1 + s2) * (1.f / 3.f);
        float var = ((s0 - mean) * (s0 - mean) + (s1 - mean) * (s1 - mean) +
                     (s2 - mean) * (s2 - mean)) * (1.f / 3.f);
        float r = rsqrtf(var + EPS_);
        g_lw[0] = (s0 - mean) * r;
        g_lw[1] = (s1 - mean) * r;
        g_lw[2] = (s2 - mean) * r;
    }
}

// ---------------- generic C = A(MxK) * B(NxK)^T, all dims % 128-compatible ----------------
__global__ __launch_bounds__(256) void gemm_abt(
    const float* __restrict__ A, const float* __restrict__ Bw,
    float* __restrict__ C, int M, int N, int K) {
    __shared__ float As[8][128];
    __shared__ float Bs[8][128];
    const int tid = threadIdx.x;
    const int m0 = blockIdx.y * 128, n0 = blockIdx.x * 128;
    const int tr = tid >> 4, tc = tid & 15;
    const int lr = tid >> 1, lk = (tid & 1) * 4;
    const float* Ap = A + (size_t)(m0 + lr) * K + lk;
    const float* Bp = Bw + (size_t)(n0 + lr) * K + lk;
    float acc[8][8];
#pragma unroll
    for (int i = 0; i < 8; i++)
#pragma unroll
        for (int j = 0; j < 8; j++) acc[i][j] = 0.f;

    for (int k0 = 0; k0 < K; k0 += 8) {
        float4 av = *(const float4*)(Ap + k0);
        float4 bv = *(const float4*)(Bp + k0);
        __syncthreads();
        As[lk + 0][lr] = av.x; As[lk + 1][lr] = av.y;
        As[lk + 2][lr] = av.z; As[lk + 3][lr] = av.w;
        Bs[lk + 0][lr] = bv.x; Bs[lk + 1][lr] = bv.y;
        Bs[lk + 2][lr] = bv.z; Bs[lk + 3][lr] = bv.w;
        __syncthreads();
#pragma unroll
        for (int kk = 0; kk < 8; kk++) {
            float a[8], b[8];
            *(float4*)(a)     = *(const float4*)&As[kk][tr * 8];
            *(float4*)(a + 4) = *(const float4*)&As[kk][tr * 8 + 4];
            *(float4*)(b)     = *(const float4*)&Bs[kk][tc * 8];
            *(float4*)(b + 4) = *(const float4*)&Bs[kk][tc * 8 + 4];
#pragma unroll
            for (int i = 0; i < 8; i++)
#pragma unroll
                for (int j = 0; j < 8; j++) acc[i][j] += a[i] * b[j];
        }
    }
#pragma unroll
    for (int i = 0; i < 8; i++) {
        float* cp = C + (size_t)(m0 + tr * 8 + i) * N + n0 + tc * 8;
        *(float4*)cp       = make_float4(acc[i][0], acc[i][1], acc[i][2], acc[i][3]);
        *(float4*)(cp + 4) = make_float4(acc[i][4], acc[i][5], acc[i][6], acc[i][7]);
    }
}

// ---------------- rope on q, in place (positions 0..T-1) ----------------
__global__ __launch_bounds__(256) void rope_q_kernel(
    const float* __restrict__ cosT, const float* __restrict__ sinT) {
    int idx = blockIdx.x * blockDim.x + threadIdx.x;  // exactly NL*MT*H*32 threads
    int d = idx & 31;
    int h = (idx >> 5) & 15;
    int bt = (idx >> 9) & 2047;
    int l = idx >> 20;
    int t = bt & 1023;
    float c = cosT[t * 32 + d];
    float s = sinT[t * 32 + d];
    float* p = g_q + ((size_t)l * MT_ + bt) * D_ + h * HD_ + d;
    float x1 = p[0], x2 = p[32];
    p[0]  = x1 * c - x2 * s;
    p[32] = x2 * c + x1 * s;
}

// ---------------- rope k + scatter K/V into caches (position = l*T + t) ----------------
__global__ __launch_bounds__(256) void rope_kv_kernel(
    const float* __restrict__ cosT, const float* __restrict__ sinT) {
    int idx = blockIdx.x * blockDim.x + threadIdx.x;  // exactly NL*MT*HKV*32 threads
    int d = idx & 31;
    int hkv = (idx >> 5) & 7;
    int bt = (idx >> 8) & 2047;
    int l = idx >> 19;
    int b = bt >> 10, t = bt & 1023;
    int pos = l * T_ + t;
    float c = cosT[pos * 32 + d];
    float s = sinT[pos * 32 + d];
    const float* kp = g_k + ((size_t)l * MT_ + bt) * (D_ / 2) + hkv * HD_ + d;
    float k1 = kp[0], k2 = kp[32];
    float* kd = g_Kc + (((size_t)b * HKV_ + hkv) * MAXKV_ + pos) * HD_ + d;
    kd[0]  = k1 * c - k2 * s;
    kd[32] = k2 * c + k1 * s;
    const float* vp = g_v + ((size_t)l * MT_ + bt) * (D_ / 2) + hkv * HD_ + d;
    float* vd = g_Vc + (((size_t)b * HKV_ + hkv) * MAXKV_ + pos) * HD_ + d;
    vd[0]  = vp[0];
    vd[32] = vp[32];
}

// ---------------- flash attention: 64x64 tiles, 128 threads, 4x8 micro-tile ----------------
__global__ __launch_bounds__(128) void attn_kernel() {
    extern __shared__ float sm[];
    float* Qt = sm;               // [64 kk][64 r]  (transposed, scaled)
    float* Kt = sm + 64 * SMS;    // [64 kk][64 c]  (transposed)
    float* Vs = sm + 2 * 64 * SMS;// [64 kv][64 d]
    float* Pt = sm + 3 * 64 * SMS;// [64 r][64 c]
    const int tid = threadIdx.x;
    const int ry = tid >> 3;      // 0..15  -> rows ry*4..+3
    const int cx = tid & 7;       // 0..7   -> cols cx*8..+7
    const int l = blockIdx.z >> 1, b = blockIdx.z & 1;
    const int h = blockIdx.y, hkv = h >> 1;
    const int t0 = blockIdx.x * 64;

    const float* qbase = g_q + (size_t)(l * MT_ + b * T_ + t0) * D_ + h * HD_;
#pragma unroll
    for (int it = 0; it < 8; it++) {
        int fl = tid + it * 128;
        int r = fl >> 4, d4 = (fl & 15) * 4;
        float4 v = *(const float4*)(qbase + (size_t)r * D_ + d4);
        Qt[(d4 + 0) * SMS + r] = v.x * 0.125f;
        Qt[(d4 + 1) * SMS + r] = v.y * 0.125f;
        Qt[(d4 + 2) * SMS + r] = v.z * 0.125f;
        Qt[(d4 + 3) * SMS + r] = v.w * 0.125f;
    }

    float m[4], lsum[4], o[4][8];
#pragma unroll
    for (int i = 0; i < 4; i++) {
        m[i] = -INFINITY; lsum[i] = 0.f;
#pragma unroll
        for (int j = 0; j < 8; j++) o[i][j] = 0.f;
    }

    const size_t kvoff = (size_t)(b * HKV_ + hkv) * MAXKV_ * HD_;
    const float* kbase = g_Kc + kvoff;
    const float* vbase = g_Vc + kvoff;
    const int nkb = l * 16 + blockIdx.x + 1;   // last chunk is the diagonal one

    for (int kb = 0; kb < nkb; kb++) {
        __syncthreads();
#pragma unroll
        for (int it = 0; it < 8; it++) {
            int fl = tid + it * 128;
            int r = fl >> 4, d4 = (fl & 15) * 4;
            float4 kv = *(const float4*)(kbase + (size_t)(kb * 64 + r) * HD_ + d4);
            Kt[(d4 + 0) * SMS + r] = kv.x;
            Kt[(d4 + 1) * SMS + r] = kv.y;
            Kt[(d4 + 2) * SMS + r] = kv.z;
            Kt[(d4 + 3) * SMS + r] = kv.w;
            float4 vv = *(const float4*)(vbase + (size_t)(kb * 64 + r) * HD_ + d4);
            *(float4*)&Vs[r * SMS + d4] = vv;
        }
        __syncthreads();

        float sacc[4][8];
#pragma unroll
        for (int i = 0; i < 4; i++)
#pragma unroll
            for (int j = 0; j < 8; j++) sacc[i][j] = 0.f;

#pragma unroll 8
        for (int kk = 0; kk < 64; kk++) {
            float4 qa = *(const float4*)&Qt[kk * SMS + ry * 4];
            float4 k0 = *(const float4*)&Kt[kk * SMS + cx * 8];
            float4 k1 = *(const float4*)&Kt[kk * SMS + cx * 8 + 4];
            float qv[4] = {qa.x, qa.y, qa.z, qa.w};
            float kv[8] = {k0.x, k0.y, k0.z, k0.w, k1.x, k1.y, k1.z, k1.w};
#pragma unroll
            for (int i = 0; i < 4; i++)
#pragma unroll
                for (int j = 0; j < 8; j++) sacc[i][j] += qv[i] * kv[j];
        }

        if (kb == nkb - 1) {  // diagonal chunk: causal mask (col > row masked)
#pragma unroll
            for (int i = 0; i < 4; i++)
#pragma unroll
                for (int j = 0; j < 8; j++)
                    if (cx * 8 + j > ry * 4 + i) sacc[i][j] = -1e30f;
        }

        float mc[4];
#pragma unroll
        for (int i = 0; i < 4; i++) {
            float v = sacc[i][0];
#pragma unroll
            for (int j = 1; j < 8; j++) v = fmaxf(v, sacc[i][j]);
            mc[i] = v;
        }
#pragma unroll
        for (int off = 4; off; off >>= 1)
#pragma unroll
            for (int i = 0; i < 4; i++)
                mc[i] = fmaxf(mc[i], __shfl_xor_sync(0xffffffffu, mc[i], off));

        float fac[4], ps[4];
#pragma unroll
        for (int i = 0; i < 4; i++) {
            float mn = fmaxf(m[i], mc[i]);
            fac[i] = __expf(m[i] - mn);
            m[i] = mn;
            ps[i] = 0.f;
        }
#pragma unroll
        for (int i = 0; i < 4; i++)
#pragma unroll
            for (int j = 0; j < 8; j++) {
                float p = __expf(sacc[i][j] - m[i]);
                sacc[i][j] = p;
                ps[i] += p;
            }
#pragma unroll
        for (int off = 4; off; off >>= 1)
#pragma unroll
            for (int i = 0; i < 4; i++)
                ps[i] += __shfl_xor_sync(0xffffffffu, ps[i], off);
#pragma unroll
        for (int i = 0; i < 4; i++) {
            lsum[i] = lsum[i] * fac[i] + ps[i];
#pragma unroll
            for (int j = 0; j < 8; j++) o[i][j] *= fac[i];
        }

#pragma unroll
        for (int i = 0; i < 4; i++) {
            int r = ry * 4 + i;
            *(float4*)&Pt[r * SMS + cx * 8] =
                make_float4(sacc[i][0], sacc[i][1], sacc[i][2], sacc[i][3]);
            *(float4*)&Pt[r * SMS + cx * 8 + 4] =
                make_float4(sacc[i][4], sacc[i][5], sacc[i][6], sacc[i][7]);
        }
        __syncthreads();

#pragma unroll 8
        for (int kk = 0; kk < 64; kk++) {
            float4 v0 = *(const float4*)&Vs[kk * SMS + cx * 8];
            float4 v1 = *(const float4*)&Vs[kk * SMS + cx * 8 + 4];
            float pr[4];
#pragma unroll
            for (int i = 0; i < 4; i++) pr[i] = Pt[(ry * 4 + i) * SMS + kk];
            float vv[8] = {v0.x, v0.y, v0.z, v0.w, v1.x, v1.y, v1.z, v1.w};
#pragma unroll
            for (int i = 0; i < 4; i++)
#pragma unroll
                for (int j = 0; j < 8; j++) o[i][j] += pr[i] * vv[j];
        }
    }

    float* obase = g_o + (size_t)(l * MT_ + b * T_ + t0) * D_ + h * HD_;
#pragma unroll
    for (int i = 0; i < 4; i++) {
        float inv = 1.f / lsum[i];
        float* op = obase + (size_t)(ry * 4 + i) * D_ + cx * 8;
        *(float4*)op = make_float4(o[i][0] * inv, o[i][1] * inv, o[i][2] * inv, o[i][3] * inv);
        *(float4*)(op + 4) = make_float4(o[i][4] * inv, o[i][5] * inv, o[i][6] * inv, o[i][7] * inv);
    }
}

// ---------------- rmsnorm-combine + final rmsnorm ----------------
__device__ __forceinline__ float blk_sum(float v, float* sred) {
#pragma unroll
    for (int off = 16; off; off >>= 1) v += __shfl_xor_sync(0xffffffffu, v, off);
    int w = threadIdx.x >> 5;
    if ((threadIdx.x & 31) == 0) sred[w] = v;
    __syncthreads();
    if (threadIdx.x < 32) {
        float t = (threadIdx.x < 8) ? sred[threadIdx.x] : 0.f;
#pragma unroll
        for (int off = 4; off; off >>= 1) t += __shfl_xor_sync(0xffffffffu, t, off);
        if (threadIdx.x == 0) sred[8] = t;
    }
    __syncthreads();
    return sred[8];
}

__global__ __launch_bounds__(256) void combine_kernel(
    const float* __restrict__ x, const float* __restrict__ ln_w,
    const float* __restrict__ final_ln_w, const float* __restrict__ alpha) {
    __shared__ float sred[9];
    const int row = blockIdx.x;
    const int d = threadIdx.x * 4;
    float4 a[NL_];
    float rl[NL_];
#pragma unroll
    for (int l2 = 0; l2 < NL_; l2++)
        a[l2] = *(const float4*)(g_o + ((size_t)l2 * MT_ + row) * D_ + d);
#pragma unroll
    for (int l2 = 0; l2 < NL_; l2++) {
        float s = a[l2].x * a[l2].x + a[l2].y * a[l2].y +
                  a[l2].z * a[l2].z + a[l2].w * a[l2].w;
        float tot = blk_sum(s, sred);
        rl[l2] = rsqrtf(tot * (1.f / D_) + EPS_) * g_lw[l2];
    }
    float4 xv = *(const float4*)(x + (size_t)row * D_ + d);
    float al = alpha[0];
    float4 acc = make_float4(al * xv.x, al * xv.y, al * xv.z, al * xv.w);
#pragma unroll
    for (int l2 = 0; l2 < NL_; l2++) {
        float4 w = *(const float4*)(ln_w + l2 * D_ + d);
        acc.x += a[l2].x * rl[l2] * w.x;
        acc.y += a[l2].y * rl[l2] * w.y;
        acc.z += a[l2].z * rl[l2] * w.z;
        acc.w += a[l2].w * rl[l2] * w.w;
    }
    float s2 = acc.x * acc.x + acc.y * acc.y + acc.z * acc.z + acc.w * acc.w;
    float rf = rsqrtf(blk_sum(s2, sred) * (1.f / D_) + EPS_);
    float4 fw = *(const float4*)(final_ln_w + d);
    *(float4*)(g_y + (size_t)row * D_ + d) =
        make_float4(acc.x * rf * fw.x, acc.y * rf * fw.y,
                    acc.z * rf * fw.z, acc.w * rf * fw.w);
}

// ---------------- launch ----------------
extern "C" void kernel_launch(void* const* d_in, const int* in_sizes, int n_in,
                              void* d_out, int out_size) {
    const float* x          = (const float*)d_in[0];
    const float* cosT       = (const float*)d_in[1];
    const float* sinT       = (const float*)d_in[2];
    const float* q_w        = (const float*)d_in[3];
    const float* k_w        = (const float*)d_in[4];
    const float* v_w        = (const float*)d_in[5];
    const float* ln_w       = (const float*)d_in[6];
    const float* lam        = (const float*)d_in[7];
    const float* out_w      = (const float*)d_in[8];
    const float* final_ln_w = (const float*)d_in[9];
    const float* alpha      = (const float*)d_in[10];

    float *p_q, *p_k, *p_v, *p_y;
    cudaGetSymbolAddress((void**)&p_q, g_q);
    cudaGetSymbolAddress((void**)&p_k, g_k);
    cudaGetSymbolAddress((void**)&p_v, g_v);
    cudaGetSymbolAddress((void**)&p_y, g_y);

    cudaFuncSetAttribute(attn_kernel, cudaFuncAttributeMaxDynamicSharedMemorySize, ATTN_SMEM);

    k_prep<<<1, 32>>>(lam);
    for (int l = 0; l < NL_; l++) {
        gemm_abt<<<dim3(8, 16), 256>>>(x, q_w + (size_t)l * D_ * D_,
                                       p_q + (size_t)l * MT_ * D_, MT_, D_, D_);
        gemm_abt<<<dim3(4, 16), 256>>>(x, k_w + (size_t)l * (D_ / 2) * D_,
                                       p_k + (size_t)l * MT_ * (D_ / 2), MT_, D_ / 2, D_);
        gemm_abt<<<dim3(4, 16), 256>>>(x, v_w + (size_t)l * (D_ / 2) * D_,
                                       p_v + (size_t)l * MT_ * (D_ / 2), MT_, D_ / 2, D_);
    }
    rope_q_kernel<<<(NL_ * MT_ * H_ * 32) / 256, 256>>>(cosT, sinT);
    rope_kv_kernel<<<(NL_ * MT_ * HKV_ * 32) / 256, 256>>>(cosT, sinT);
    attn_kernel<<<dim3(16, 16, NL_ * B_), 128, ATTN_SMEM>>>();
    combine_kernel<<<MT_, 256>>>(x, ln_w, final_ln_w, alpha);
    gemm_abt<<<dim3(8, 16), 256>>>(p_y, out_w, (float*)d_out, MT_, D_, D_);
}

// round 5
// speedup vs baseline: 1.0847x; 1.0847x over previous
#include <cuda_runtime.h>
#include <cuda_bf16.h>
#include <math.h>
#include <stdint.h>

#define B_ 2
#define T_ 1024
#define D_ 1024
#define H_ 16
#define HKV_ 8
#define HD_ 64
#define NL_ 3
#define MAXKV_ 3072
#define MT_ 2048
#define EPS_ 1e-5f
#define SMS 68
#define ATTN_SMEM (4 * 64 * SMS * (int)sizeof(float))
#define QKVW_ 2048
#define GSMEM (2 * 4 * 16384)   // 2 stages x 4 matrices x 16KB

// ---------------- scratch ----------------
__device__ __align__(256) float g_qkv[NL_ * MT_ * QKVW_];
__device__ __align__(256) float g_Kc[B_ * HKV_ * MAXKV_ * HD_];
__device__ __align__(256) float g_Vc[B_ * HKV_ * MAXKV_ * HD_];
__device__ __align__(256) float g_o[NL_ * MT_ * D_];
__device__ __align__(256) __nv_bfloat16 g_xhi[MT_ * D_];
__device__ __align__(256) __nv_bfloat16 g_xlo[MT_ * D_];
__device__ __align__(256) __nv_bfloat16 g_wqkv_hi[NL_ * QKVW_ * D_];
__device__ __align__(256) __nv_bfloat16 g_wqkv_lo[NL_ * QKVW_ * D_];
__device__ __align__(256) __nv_bfloat16 g_wo_hi[D_ * D_];
__device__ __align__(256) __nv_bfloat16 g_wo_lo[D_ * D_];
__device__ __align__(256) __nv_bfloat16 g_yhi[MT_ * D_];
__device__ __align__(256) __nv_bfloat16 g_ylo[MT_ * D_];
__device__ float g_lw[NL_];

// ---------------- helpers ----------------
__device__ __forceinline__ uint32_t smem_u32(const void* p) {
    uint32_t a;
    asm("{ .reg .u64 t; cvta.to.shared.u64 t, %1; cvt.u32.u64 %0, t; }" : "=r"(a) : "l"(p));
    return a;
}
__device__ __forceinline__ void cp_async16(uint32_t dst, const void* src) {
    asm volatile("cp.async.cg.shared.global [%0], [%1], 16;\n" :: "r"(dst), "l"(src));
}
__device__ __forceinline__ void cp_commit() { asm volatile("cp.async.commit_group;\n"); }
__device__ __forceinline__ void cp_wait1() { asm volatile("cp.async.wait_group 1;\n" ::: "memory"); }
__device__ __forceinline__ void cp_wait0() { asm volatile("cp.async.wait_group 0;\n" ::: "memory"); }

__device__ __forceinline__ void ldm_x4(uint32_t* r, uint32_t addr) {
    asm volatile("ldmatrix.sync.aligned.m8n8.x4.shared.b16 {%0,%1,%2,%3}, [%4];"
                 : "=r"(r[0]), "=r"(r[1]), "=r"(r[2]), "=r"(r[3]) : "r"(addr));
}
__device__ __forceinline__ void ldm_x2(uint32_t* r, uint32_t addr) {
    asm volatile("ldmatrix.sync.aligned.m8n8.x2.shared.b16 {%0,%1}, [%2];"
                 : "=r"(r[0]), "=r"(r[1]) : "r"(addr));
}
__device__ __forceinline__ void mma16816(float* c, const uint32_t* a, const uint32_t* b) {
    asm volatile(
        "mma.sync.aligned.m16n8k16.row.col.f32.bf16.bf16.f32 "
        "{%0,%1,%2,%3}, {%4,%5,%6,%7}, {%8,%9}, {%0,%1,%2,%3};"
        : "+f"(c[0]), "+f"(c[1]), "+f"(c[2]), "+f"(c[3])
        : "r"(a[0]), "r"(a[1]), "r"(a[2]), "r"(a[3]), "r"(b[0]), "r"(b[1]));
}
#define SWZ(x) ((x) ^ (((x) >> 3) & 0x70))

// ---------------- lambda prep ----------------
__global__ void k_prep(const float* __restrict__ lam) {
    if (threadIdx.x == 0) {
        float s0 = 1.f / (1.f + expf(-lam[0]));
        float s1 = 1.f / (1.f + expf(-lam[1]));
        float s2 = 1.f / (1.f + expf(-lam[2]));
        float mean = (s0 + s1 + s2) * (1.f / 3.f);
        float var = ((s0 - mean) * (s0 - mean) + (s1 - mean) * (s1 - mean) +
                     (s2 - mean) * (s2 - mean)) * (1.f / 3.f);
        float r = rsqrtf(var + EPS_);
        g_lw[0] = (s0 - mean) * r;
        g_lw[1] = (s1 - mean) * r;
        g_lw[2] = (s2 - mean) * r;
    }
}

// ---------------- bf16 split preps ----------------
__global__ __launch_bounds__(256) void split_f32(const float* __restrict__ src,
                                                 __nv_bfloat16* __restrict__ hi,
                                                 __nv_bfloat16* __restrict__ lo) {
    int i = blockIdx.x * 256 + threadIdx.x;
    float f = src[i];
    __nv_bfloat16 h = __float2bfloat16(f);
    hi[i] = h;
    lo[i] = __float2bfloat16(f - __bfloat162float(h));
}

__global__ __launch_bounds__(256) void pack_wqkv(const float* __restrict__ q_w,
                                                 const float* __restrict__ k_w,
                                                 const float* __restrict__ v_w) {
    int i = blockIdx.x * 256 + threadIdx.x;  // 3*2048*1024 total
    int kk = i & 1023;
    int r = (i >> 10) & 2047;
    int l = i >> 21;
    float f;
    if (r < 1024)       f = q_w[(size_t)l * 1048576 + (size_t)r * 1024 + kk];
    else if (r < 1536)  f = k_w[(size_t)l * 524288 + (size_t)(r - 1024) * 1024 + kk];
    else                f = v_w[(size_t)l * 524288 + (size_t)(r - 1536) * 1024 + kk];
    __nv_bfloat16 h = __float2bfloat16(f);
    g_wqkv_hi[i] = h;
    g_wqkv_lo[i] = __float2bfloat16(f - __bfloat162float(h));
}

// ---------------- bf16x3 tensor-core GEMM via mma.sync ----------------
// C[z] (M x N tile grid) = A(M x 1024) * B[z](N x 1024)^T, fp32 out
__global__ __launch_bounds__(256, 1) void gemm_tc(
    const __nv_bfloat16* __restrict__ Ahi, const __nv_bfloat16* __restrict__ Alo,
    const __nv_bfloat16* __restrict__ Bhi, const __nv_bfloat16* __restrict__ Blo,
    float* __restrict__ C, int bRows, int ldc, long strideC) {
    extern __shared__ char sm[];
    const uint32_t sb = smem_u32(sm);
    const int tid = threadIdx.x;
    const int wid = tid >> 5, lane = tid & 31;
    const int wm = wid & 1, wn = wid >> 1;     // warp tile: rows wm*64, cols wn*32
    const int n0 = blockIdx.x * 128, m0 = blockIdx.y * 128, z = blockIdx.z;
    const int K = 1024, NK = 16;

    const __nv_bfloat16* srcp[4] = {
        Ahi + (size_t)m0 * K, Alo + (size_t)m0 * K,
        Bhi + ((size_t)z * bRows + n0) * K, Blo + ((size_t)z * bRows + n0) * K};

    // preload chunk 0 -> stage 0
#pragma unroll
    for (int it = 0; it < 16; it++) {
        int idx = tid + it * 256;
        int t = idx >> 10, row = (idx >> 3) & 127, seg = idx & 7;
        cp_async16(sb + t * 16384 + SWZ(row * 128 + seg * 16),
                   srcp[t] + (size_t)row * K + seg * 8);
    }
    cp_commit();

    float acc[4][4][4];
#pragma unroll
    for (int mi = 0; mi < 4; mi++)
#pragma unroll
        for (int ni = 0; ni < 4; ni++)
#pragma unroll
            for (int q = 0; q < 4; q++) acc[mi][ni][q] = 0.f;

    const int r8 = lane & 7, mat = lane >> 3;
    const int lb = lane & 15, matb = lb >> 3, r8b = lb & 7;

    for (int kc = 0; kc < NK; kc++) {
        const uint32_t cb = sb + (kc & 1) * 65536;
        if (kc + 1 < NK) {
            const uint32_t db = sb + ((kc + 1) & 1) * 65536;
            const int ko = (kc + 1) * 64;
#pragma unroll
            for (int it = 0; it < 16; it++) {
                int idx = tid + it * 256;
                int t = idx >> 10, row = (idx >> 3) & 127, seg = idx & 7;
                cp_async16(db + t * 16384 + SWZ(row * 128 + seg * 16),
                           srcp[t] + (size_t)row * K + ko + seg * 8);
            }
            cp_commit();
            cp_wait1();
        } else {
            cp_wait0();
        }
        __syncthreads();

#pragma unroll
        for (int ks = 0; ks < 4; ks++) {
            uint32_t bhi[4][2], blo[4][2];
#pragma unroll
            for (int ni = 0; ni < 4; ni++) {
                uint32_t brow = wn * 32 + ni * 8 + r8b;
                uint32_t bbyte = ks * 32 + matb * 16;
                uint32_t off = SWZ(brow * 128 + bbyte);
                ldm_x2(bhi[ni], cb + 32768 + off);
                ldm_x2(blo[ni], cb + 49152 + off);
            }
#pragma unroll
            for (int mi = 0; mi < 4; mi++) {
                uint32_t arow = wm * 64 + mi * 16 + r8 + (mat & 1) * 8;
                uint32_t abyte = ks * 32 + (mat >> 1) * 16;
                uint32_t off = SWZ(arow * 128 + abyte);
                uint32_t ahi[4], alo[4];
                ldm_x4(ahi, cb + off);
                ldm_x4(alo, cb + 16384 + off);
#pragma unroll
                for (int ni = 0; ni < 4; ni++) {
                    mma16816(acc[mi][ni], ahi, bhi[ni]);
                    mma16816(acc[mi][ni], ahi, blo[ni]);
                    mma16816(acc[mi][ni], alo, bhi[ni]);
                }
            }
        }
        __syncthreads();
    }

    // epilogue
    float* cz = C + (size_t)z * strideC;
#pragma unroll
    for (int mi = 0; mi < 4; mi++) {
        int row0 = m0 + wm * 64 + mi * 16 + (lane >> 2);
#pragma unroll
        for (int ni = 0; ni < 4; ni++) {
            int col = n0 + wn * 32 + ni * 8 + (lane & 3) * 2;
            *(float2*)(cz + (size_t)row0 * ldc + col) =
                make_float2(acc[mi][ni][0], acc[mi][ni][1]);
            *(float2*)(cz + (size_t)(row0 + 8) * ldc + col) =
                make_float2(acc[mi][ni][2], acc[mi][ni][3]);
        }
    }
}

// ---------------- rope on q (cols [0,1024) of g_qkv) ----------------
__global__ __launch_bounds__(256) void rope_q_kernel(
    const float* __restrict__ cosT, const float* __restrict__ sinT) {
    int idx = blockIdx.x * blockDim.x + threadIdx.x;
    int d = idx & 31;
    int h = (idx >> 5) & 15;
    int bt = (idx >> 9) & 2047;
    int l = idx >> 20;
    int t = bt & 1023;
    float c = cosT[t * 32 + d];
    float s = sinT[t * 32 + d];
    float* p = g_qkv + ((size_t)l * MT_ + bt) * QKVW_ + h * HD_ + d;
    float x1 = p[0], x2 = p[32];
    p[0] = x1 * c - x2 * s;
    p[32] = x2 * c + x1 * s;
}

// ---------------- rope k + scatter K/V ----------------
__global__ __launch_bounds__(256) void rope_kv_kernel(
    const float* __restrict__ cosT, const float* __restrict__ sinT) {
    int idx = blockIdx.x * blockDim.x + threadIdx.x;
    int d = idx & 31;
    int hkv = (idx >> 5) & 7;
    int bt = (idx >> 8) & 2047;
    int l = idx >> 19;
    int b = bt >> 10, t = bt & 1023;
    int pos = l * T_ + t;
    float c = cosT[pos * 32 + d];
    float s = sinT[pos * 32 + d];
    const float* row = g_qkv + ((size_t)l * MT_ + bt) * QKVW_;
    const float* kp = row + 1024 + hkv * HD_ + d;
    float k1 = kp[0], k2 = kp[32];
    float* kd = g_Kc + (((size_t)b * HKV_ + hkv) * MAXKV_ + pos) * HD_ + d;
    kd[0] = k1 * c - k2 * s;
    kd[32] = k2 * c + k1 * s;
    const float* vp = row + 1536 + hkv * HD_ + d;
    float* vd = g_Vc + (((size_t)b * HKV_ + hkv) * MAXKV_ + pos) * HD_ + d;
    vd[0] = vp[0];
    vd[32] = vp[32];
}

// ---------------- flash attention (fp32, q from g_qkv stride 2048) ----------------
__global__ __launch_bounds__(128) void attn_kernel() {
    extern __shared__ float smf[];
    float* Qt = smf;
    float* Kt = smf + 64 * SMS;
    float* Vs = smf + 2 * 64 * SMS;
    float* Pt = smf + 3 * 64 * SMS;
    const int tid = threadIdx.x;
    const int ry = tid >> 3;
    const int cx = tid & 7;
    const int l = blockIdx.z >> 1, b = blockIdx.z & 1;
    const int h = blockIdx.y, hkv = h >> 1;
    const int t0 = blockIdx.x * 64;

    const float* qbase = g_qkv + (size_t)(l * MT_ + b * T_ + t0) * QKVW_ + h * HD_;
#pragma unroll
    for (int it = 0; it < 8; it++) {
        int fl = tid + it * 128;
        int r = fl >> 4, d4 = (fl & 15) * 4;
        float4 v = *(const float4*)(qbase + (size_t)r * QKVW_ + d4);
        Qt[(d4 + 0) * SMS + r] = v.x * 0.125f;
        Qt[(d4 + 1) * SMS + r] = v.y * 0.125f;
        Qt[(d4 + 2) * SMS + r] = v.z * 0.125f;
        Qt[(d4 + 3) * SMS + r] = v.w * 0.125f;
    }

    float m[4], lsum[4], o[4][8];
#pragma unroll
    for (int i = 0; i < 4; i++) {
        m[i] = -INFINITY; lsum[i] = 0.f;
#pragma unroll
        for (int j = 0; j < 8; j++) o[i][j] = 0.f;
    }

    const size_t kvoff = (size_t)(b * HKV_ + hkv) * MAXKV_ * HD_;
    const float* kbase = g_Kc + kvoff;
    const float* vbase = g_Vc + kvoff;
    const int nkb = l * 16 + blockIdx.x + 1;

    for (int kb = 0; kb < nkb; kb++) {
        __syncthreads();
#pragma unroll
        for (int it = 0; it < 8; it++) {
            int fl = tid + it * 128;
            int r = fl >> 4, d4 = (fl & 15) * 4;
            float4 kv = *(const float4*)(kbase + (size_t)(kb * 64 + r) * HD_ + d4);
            Kt[(d4 + 0) * SMS + r] = kv.x;
            Kt[(d4 + 1) * SMS + r] = kv.y;
            Kt[(d4 + 2) * SMS + r] = kv.z;
            Kt[(d4 + 3) * SMS + r] = kv.w;
            float4 vv = *(const float4*)(vbase + (size_t)(kb * 64 + r) * HD_ + d4);
            *(float4*)&Vs[r * SMS + d4] = vv;
        }
        __syncthreads();

        float sacc[4][8];
#pragma unroll
        for (int i = 0; i < 4; i++)
#pragma unroll
            for (int j = 0; j < 8; j++) sacc[i][j] = 0.f;

#pragma unroll 8
        for (int kk = 0; kk < 64; kk++) {
            float4 qa = *(const float4*)&Qt[kk * SMS + ry * 4];
            float4 k0 = *(const float4*)&Kt[kk * SMS + cx * 8];
            float4 k1 = *(const float4*)&Kt[kk * SMS + cx * 8 + 4];
            float qv[4] = {qa.x, qa.y, qa.z, qa.w};
            float kv[8] = {k0.x, k0.y, k0.z, k0.w, k1.x, k1.y, k1.z, k1.w};
#pragma unroll
            for (int i = 0; i < 4; i++)
#pragma unroll
                for (int j = 0; j < 8; j++) sacc[i][j] += qv[i] * kv[j];
        }

        if (kb == nkb - 1) {
#pragma unroll
            for (int i = 0; i < 4; i++)
#pragma unroll
                for (int j = 0; j < 8; j++)
                    if (cx * 8 + j > ry * 4 + i) sacc[i][j] = -1e30f;
        }

        float mc[4];
#pragma unroll
        for (int i = 0; i < 4; i++) {
            float v = sacc[i][0];
#pragma unroll
            for (int j = 1; j < 8; j++) v = fmaxf(v, sacc[i][j]);
            mc[i] = v;
        }
#pragma unroll
        for (int off = 4; off; off >>= 1)
#pragma unroll
            for (int i = 0; i < 4; i++)
                mc[i] = fmaxf(mc[i], __shfl_xor_sync(0xffffffffu, mc[i], off));

        float fac[4], ps[4];
#pragma unroll
        for (int i = 0; i < 4; i++) {
            float mn = fmaxf(m[i], mc[i]);
            fac[i] = __expf(m[i] - mn);
            m[i] = mn;
            ps[i] = 0.f;
        }
#pragma unroll
        for (int i = 0; i < 4; i++)
#pragma unroll
            for (int j = 0; j < 8; j++) {
                float p = __expf(sacc[i][j] - m[i]);
                sacc[i][j] = p;
                ps[i] += p;
            }
#pragma unroll
        for (int off = 4; off; off >>= 1)
#pragma unroll
            for (int i = 0; i < 4; i++)
                ps[i] += __shfl_xor_sync(0xffffffffu, ps[i], off);
#pragma unroll
        for (int i = 0; i < 4; i++) {
            lsum[i] = lsum[i] * fac[i] + ps[i];
#pragma unroll
            for (int j = 0; j < 8; j++) o[i][j] *= fac[i];
        }

#pragma unroll
        for (int i = 0; i < 4; i++) {
            int r = ry * 4 + i;
            *(float4*)&Pt[r * SMS + cx * 8] =
                make_float4(sacc[i][0], sacc[i][1], sacc[i][2], sacc[i][3]);
            *(float4*)&Pt[r * SMS + cx * 8 + 4] =
                make_float4(sacc[i][4], sacc[i][5], sacc[i][6], sacc[i][7]);
        }
        __syncthreads();

#pragma unroll 8
        for (int kk = 0; kk < 64; kk++) {
            float4 v0 = *(const float4*)&Vs[kk * SMS + cx * 8];
            float4 v1 = *(const float4*)&Vs[kk * SMS + cx * 8 + 4];
            float pr[4];
#pragma unroll
            for (int i = 0; i < 4; i++) pr[i] = Pt[(ry * 4 + i) * SMS + kk];
            float vv[8] = {v0.x, v0.y, v0.z, v0.w, v1.x, v1.y, v1.z, v1.w};
#pragma unroll
            for (int i = 0; i < 4; i++)
#pragma unroll
                for (int j = 0; j < 8; j++) o[i][j] += pr[i] * vv[j];
        }
    }

    float* obase = g_o + (size_t)(l * MT_ + b * T_ + t0) * D_ + h * HD_;
#pragma unroll
    for (int i = 0; i < 4; i++) {
        float inv = 1.f / lsum[i];
        float* op = obase + (size_t)(ry * 4 + i) * D_ + cx * 8;
        *(float4*)op = make_float4(o[i][0] * inv, o[i][1] * inv, o[i][2] * inv, o[i][3] * inv);
        *(float4*)(op + 4) = make_float4(o[i][4] * inv, o[i][5] * inv, o[i][6] * inv, o[i][7] * inv);
    }
}

// ---------------- combine -> bf16-split y ----------------
__device__ __forceinline__ float blk_sum(float v, float* sred) {
#pragma unroll
    for (int off = 16; off; off >>= 1) v += __shfl_xor_sync(0xffffffffu, v, off);
    int w = threadIdx.x >> 5;
    if ((threadIdx.x & 31) == 0) sred[w] = v;
    __syncthreads();
    if (threadIdx.x < 32) {
        float t = (threadIdx.x < 8) ? sred[threadIdx.x] : 0.f;
#pragma unroll
        for (int off = 4; off; off >>= 1) t += __shfl_xor_sync(0xffffffffu, t, off);
        if (threadIdx.x == 0) sred[8] = t;
    }
    __syncthreads();
    return sred[8];
}

__global__ __launch_bounds__(256) void combine_kernel(
    const float* __restrict__ x, const float* __restrict__ ln_w,
    const float* __restrict__ final_ln_w, const float* __restrict__ alpha) {
    __shared__ float sred[9];
    const int row = blockIdx.x;
    const int d = threadIdx.x * 4;
    float4 a[NL_];
    float rl[NL_];
#pragma unroll
    for (int l2 = 0; l2 < NL_; l2++)
        a[l2] = *(const float4*)(g_o + ((size_t)l2 * MT_ + row) * D_ + d);
#pragma unroll
    for (int l2 = 0; l2 < NL_; l2++) {
        float s = a[l2].x * a[l2].x + a[l2].y * a[l2].y +
                  a[l2].z * a[l2].z + a[l2].w * a[l2].w;
        float tot = blk_sum(s, sred);
        rl[l2] = rsqrtf(tot * (1.f / D_) + EPS_) * g_lw[l2];
    }
    float4 xv = *(const float4*)(x + (size_t)row * D_ + d);
    float al = alpha[0];
    float4 acc = make_float4(al * xv.x, al * xv.y, al * xv.z, al * xv.w);
#pragma unroll
    for (int l2 = 0; l2 < NL_; l2++) {
        float4 w = *(const float4*)(ln_w + l2 * D_ + d);
        acc.x += a[l2].x * rl[l2] * w.x;
        acc.y += a[l2].y * rl[l2] * w.y;
        acc.z += a[l2].z * rl[l2] * w.z;
        acc.w += a[l2].w * rl[l2] * w.w;
    }
    float s2 = acc.x * acc.x + acc.y * acc.y + acc.z * acc.z + acc.w * acc.w;
    float rf = rsqrtf(blk_sum(s2, sred) * (1.f / D_) + EPS_);
    float4 fw = *(const float4*)(final_ln_w + d);
    float outv[4] = {acc.x * rf * fw.x, acc.y * rf * fw.y,
                     acc.z * rf * fw.z, acc.w * rf * fw.w};
    size_t base = (size_t)row * D_ + d;
#pragma unroll
    for (int j = 0; j < 4; j++) {
        __nv_bfloat16 h = __float2bfloat16(outv[j]);
        g_yhi[base + j] = h;
        g_ylo[base + j] = __float2bfloat16(outv[j] - __bfloat162float(h));
    }
}

// ---------------- launch ----------------
extern "C" void kernel_launch(void* const* d_in, const int* in_sizes, int n_in,
                              void* d_out, int out_size) {
    const float* x          = (const float*)d_in[0];
    const float* cosT       = (const float*)d_in[1];
    const float* sinT       = (const float*)d_in[2];
    const float* q_w        = (const float*)d_in[3];
    const float* k_w        = (const float*)d_in[4];
    const float* v_w        = (const float*)d_in[5];
    const float* ln_w       = (const float*)d_in[6];
    const float* lam        = (const float*)d_in[7];
    const float* out_w      = (const float*)d_in[8];
    const float* final_ln_w = (const float*)d_in[9];
    const float* alpha      = (const float*)d_in[10];

    __nv_bfloat16 *p_xhi, *p_xlo, *p_wqh, *p_wql, *p_woh, *p_wol, *p_yh, *p_yl;
    float* p_qkv;
    cudaGetSymbolAddress((void**)&p_xhi, g_xhi);
    cudaGetSymbolAddress((void**)&p_xlo, g_xlo);
    cudaGetSymbolAddress((void**)&p_wqh, g_wqkv_hi);
    cudaGetSymbolAddress((void**)&p_wql, g_wqkv_lo);
    cudaGetSymbolAddress((void**)&p_woh, g_wo_hi);
    cudaGetSymbolAddress((void**)&p_wol, g_wo_lo);
    cudaGetSymbolAddress((void**)&p_yh, g_yhi);
    cudaGetSymbolAddress((void**)&p_yl, g_ylo);
    cudaGetSymbolAddress((void**)&p_qkv, g_qkv);

    cudaFuncSetAttribute(attn_kernel, cudaFuncAttributeMaxDynamicSharedMemorySize, ATTN_SMEM);
    cudaFuncSetAttribute(gemm_tc, cudaFuncAttributeMaxDynamicSharedMemorySize, GSMEM);

    k_prep<<<1, 32>>>(lam);
    split_f32<<<(MT_ * D_) / 256, 256>>>(x, p_xhi, p_xlo);
    pack_wqkv<<<(NL_ * QKVW_ * D_) / 256, 256>>>(q_w, k_w, v_w);
    split_f32<<<(D_ * D_) / 256, 256>>>(out_w, p_woh, p_wol);

    // fused QKV projections: C[l] (2048 x 2048) = x * Wqkv[l]^T
    gemm_tc<<<dim3(16, 16, 3), 256, GSMEM>>>(p_xhi, p_xlo, p_wqh, p_wql,
                                             p_qkv, QKVW_, QKVW_,
                                             (long)MT_ * QKVW_);

    rope_q_kernel<<<(NL_ * MT_ * H_ * 32) / 256, 256>>>(cosT, sinT);
    rope_kv_kernel<<<(NL_ * MT_ * HKV_ * 32) / 256, 256>>>(cosT, sinT);
    attn_kernel<<<dim3(16, 16, NL_ * B_), 128, ATTN_SMEM>>>();
    combine_kernel<<<MT_, 256>>>(x, ln_w, final_ln_w, alpha);

    // output projection: d_out (2048 x 1024) = y * Wo^T
    gemm_tc<<<dim3(8, 16, 1), 256, GSMEM>>>(p_yh, p_yl, p_woh, p_wol,
                                            (float*)d_out, D_, D_, 0L);
}

// round 6
// speedup vs baseline: 5.7672x; 5.3170x over previous
#include <cuda_runtime.h>
#include <cuda_bf16.h>
#include <math.h>
#include <stdint.h>

#define B_ 2
#define T_ 1024
#define D_ 1024
#define H_ 16
#define HKV_ 8
#define HD_ 64
#define NL_ 3
#define MAXKV_ 3072
#define MT_ 2048
#define EPS_ 1e-5f
#define QKVW_ 2048
#define GSMEM (2 * 4 * 16384)          // gemm: 2 stages x 4 matrices x 16KB
#define ASMEM (32768 + 2 * 32768)      // attn: Qh/Ql 32KB + 2 stages x (K/V hi/lo) 32KB

// ---------------- scratch ----------------
__device__ __align__(256) float g_qkv[NL_ * MT_ * QKVW_];
__device__ __align__(256) float g_o[NL_ * MT_ * D_];
__device__ __align__(256) __nv_bfloat16 g_qh[NL_ * MT_ * D_];
__device__ __align__(256) __nv_bfloat16 g_ql[NL_ * MT_ * D_];
__device__ __align__(256) __nv_bfloat16 g_Kch[B_ * HKV_ * MAXKV_ * HD_];
__device__ __align__(256) __nv_bfloat16 g_Kcl[B_ * HKV_ * MAXKV_ * HD_];
__device__ __align__(256) __nv_bfloat16 g_Vch[B_ * HKV_ * MAXKV_ * HD_];
__device__ __align__(256) __nv_bfloat16 g_Vcl[B_ * HKV_ * MAXKV_ * HD_];
__device__ __align__(256) __nv_bfloat16 g_xhi[MT_ * D_];
__device__ __align__(256) __nv_bfloat16 g_xlo[MT_ * D_];
__device__ __align__(256) __nv_bfloat16 g_wqkv_hi[NL_ * QKVW_ * D_];
__device__ __align__(256) __nv_bfloat16 g_wqkv_lo[NL_ * QKVW_ * D_];
__device__ __align__(256) __nv_bfloat16 g_wo_hi[D_ * D_];
__device__ __align__(256) __nv_bfloat16 g_wo_lo[D_ * D_];
__device__ __align__(256) __nv_bfloat16 g_yhi[MT_ * D_];
__device__ __align__(256) __nv_bfloat16 g_ylo[MT_ * D_];
__device__ float g_lw[NL_];

// ---------------- helpers ----------------
__device__ __forceinline__ uint32_t smem_u32(const void* p) {
    uint32_t a;
    asm("{ .reg .u64 t; cvta.to.shared.u64 t, %1; cvt.u32.u64 %0, t; }" : "=r"(a) : "l"(p));
    return a;
}
__device__ __forceinline__ void cp_async16(uint32_t dst, const void* src) {
    asm volatile("cp.async.cg.shared.global [%0], [%1], 16;\n" :: "r"(dst), "l"(src));
}
__device__ __forceinline__ void cp_commit() { asm volatile("cp.async.commit_group;\n"); }
__device__ __forceinline__ void cp_wait1() { asm volatile("cp.async.wait_group 1;\n" ::: "memory"); }
__device__ __forceinline__ void cp_wait0() { asm volatile("cp.async.wait_group 0;\n" ::: "memory"); }

__device__ __forceinline__ void ldm_x4(uint32_t* r, uint32_t addr) {
    asm volatile("ldmatrix.sync.aligned.m8n8.x4.shared.b16 {%0,%1,%2,%3}, [%4];"
                 : "=r"(r[0]), "=r"(r[1]), "=r"(r[2]), "=r"(r[3]) : "r"(addr));
}
__device__ __forceinline__ void ldm_x4t(uint32_t* r, uint32_t addr) {
    asm volatile("ldmatrix.sync.aligned.m8n8.x4.trans.shared.b16 {%0,%1,%2,%3}, [%4];"
                 : "=r"(r[0]), "=r"(r[1]), "=r"(r[2]), "=r"(r[3]) : "r"(addr));
}
__device__ __forceinline__ void ldm_x2(uint32_t* r, uint32_t addr) {
    asm volatile("ldmatrix.sync.aligned.m8n8.x2.shared.b16 {%0,%1}, [%2];"
                 : "=r"(r[0]), "=r"(r[1]) : "r"(addr));
}
__device__ __forceinline__ void mma16816(float* c, const uint32_t* a, const uint32_t* b) {
    asm volatile(
        "mma.sync.aligned.m16n8k16.row.col.f32.bf16.bf16.f32 "
        "{%0,%1,%2,%3}, {%4,%5,%6,%7}, {%8,%9}, {%0,%1,%2,%3};"
        : "+f"(c[0]), "+f"(c[1]), "+f"(c[2]), "+f"(c[3])
        : "r"(a[0]), "r"(a[1]), "r"(a[2]), "r"(a[3]), "r"(b[0]), "r"(b[1]));
}
#define SWZ(x) ((x) ^ (((x) >> 3) & 0x70))

// ---------------- lambda prep ----------------
__global__ void k_prep(const float* __restrict__ lam) {
    if (threadIdx.x == 0) {
        float s0 = 1.f / (1.f + expf(-lam[0]));
        float s1 = 1.f / (1.f + expf(-lam[1]));
        float s2 = 1.f / (1.f + expf(-lam[2]));
        float mean = (s0 + s1 + s2) * (1.f / 3.f);
        float var = ((s0 - mean) * (s0 - mean) + (s1 - mean) * (s1 - mean) +
                     (s2 - mean) * (s2 - mean)) * (1.f / 3.f);
        float r = rsqrtf(var + EPS_);
        g_lw[0] = (s0 - mean) * r;
        g_lw[1] = (s1 - mean) * r;
        g_lw[2] = (s2 - mean) * r;
    }
}

// ---------------- bf16 split preps ----------------
__global__ __launch_bounds__(256) void split_f32(const float* __restrict__ src,
                                                 __nv_bfloat16* __restrict__ hi,
                                                 __nv_bfloat16* __restrict__ lo) {
    int i = blockIdx.x * 256 + threadIdx.x;
    float f = src[i];
    __nv_bfloat16 h = __float2bfloat16(f);
    hi[i] = h;
    lo[i] = __float2bfloat16(f - __bfloat162float(h));
}

__global__ __launch_bounds__(256) void pack_wqkv(const float* __restrict__ q_w,
                                                 const float* __restrict__ k_w,
                                                 const float* __restrict__ v_w) {
    int i = blockIdx.x * 256 + threadIdx.x;  // 3*2048*1024 total
    int kk = i & 1023;
    int r = (i >> 10) & 2047;
    int l = i >> 21;
    float f;
    if (r < 1024)       f = q_w[(size_t)l * 1048576 + (size_t)r * 1024 + kk];
    else if (r < 1536)  f = k_w[(size_t)l * 524288 + (size_t)(r - 1024) * 1024 + kk];
    else                f = v_w[(size_t)l * 524288 + (size_t)(r - 1536) * 1024 + kk];
    __nv_bfloat16 h = __float2bfloat16(f);
    g_wqkv_hi[i] = h;
    g_wqkv_lo[i] = __float2bfloat16(f - __bfloat162float(h));
}

// ---------------- bf16x3 tensor-core GEMM (unchanged from R5) ----------------
__global__ __launch_bounds__(256, 1) void gemm_tc(
    const __nv_bfloat16* __restrict__ Ahi, const __nv_bfloat16* __restrict__ Alo,
    const __nv_bfloat16* __restrict__ Bhi, const __nv_bfloat16* __restrict__ Blo,
    float* __restrict__ C, int bRows, int ldc, long strideC) {
    extern __shared__ char sm[];
    const uint32_t sb = smem_u32(sm);
    const int tid = threadIdx.x;
    const int wid = tid >> 5, lane = tid & 31;
    const int wm = wid & 1, wn = wid >> 1;
    const int n0 = blockIdx.x * 128, m0 = blockIdx.y * 128, z = blockIdx.z;
    const int K = 1024, NK = 16;

    const __nv_bfloat16* srcp[4] = {
        Ahi + (size_t)m0 * K, Alo + (size_t)m0 * K,
        Bhi + ((size_t)z * bRows + n0) * K, Blo + ((size_t)z * bRows + n0) * K};

#pragma unroll
    for (int it = 0; it < 16; it++) {
        int idx = tid + it * 256;
        int t = idx >> 10, row = (idx >> 3) & 127, seg = idx & 7;
        cp_async16(sb + t * 16384 + SWZ(row * 128 + seg * 16),
                   srcp[t] + (size_t)row * K + seg * 8);
    }
    cp_commit();

    float acc[4][4][4];
#pragma unroll
    for (int mi = 0; mi < 4; mi++)
#pragma unroll
        for (int ni = 0; ni < 4; ni++)
#pragma unroll
            for (int q = 0; q < 4; q++) acc[mi][ni][q] = 0.f;

    const int r8 = lane & 7, mat = lane >> 3;
    const int lb = lane & 15, matb = lb >> 3, r8b = lb & 7;

    for (int kc = 0; kc < NK; kc++) {
        const uint32_t cb = sb + (kc & 1) * 65536;
        if (kc + 1 < NK) {
            const uint32_t db = sb + ((kc + 1) & 1) * 65536;
            const int ko = (kc + 1) * 64;
#pragma unroll
            for (int it = 0; it < 16; it++) {
                int idx = tid + it * 256;
                int t = idx >> 10, row = (idx >> 3) & 127, seg = idx & 7;
                cp_async16(db + t * 16384 + SWZ(row * 128 + seg * 16),
                           srcp[t] + (size_t)row * K + ko + seg * 8);
            }
            cp_commit();
            cp_wait1();
        } else {
            cp_wait0();
        }
        __syncthreads();

#pragma unroll
        for (int ks = 0; ks < 4; ks++) {
            uint32_t bhi[4][2], blo[4][2];
#pragma unroll
            for (int ni = 0; ni < 4; ni++) {
                uint32_t brow = wn * 32 + ni * 8 + r8b;
                uint32_t bbyte = ks * 32 + matb * 16;
                uint32_t off = SWZ(brow * 128 + bbyte);
                ldm_x2(bhi[ni], cb + 32768 + off);
                ldm_x2(blo[ni], cb + 49152 + off);
            }
#pragma unroll
            for (int mi = 0; mi < 4; mi++) {
                uint32_t arow = wm * 64 + mi * 16 + r8 + (mat & 1) * 8;
                uint32_t abyte = ks * 32 + (mat >> 1) * 16;
                uint32_t off = SWZ(arow * 128 + abyte);
                uint32_t ahi[4], alo[4];
                ldm_x4(ahi, cb + off);
                ldm_x4(alo, cb + 16384 + off);
#pragma unroll
                for (int ni = 0; ni < 4; ni++) {
                    mma16816(acc[mi][ni], ahi, bhi[ni]);
                    mma16816(acc[mi][ni], ahi, blo[ni]);
                    mma16816(acc[mi][ni], alo, bhi[ni]);
                }
            }
        }
        __syncthreads();
    }

    float* cz = C + (size_t)z * strideC;
#pragma unroll
    for (int mi = 0; mi < 4; mi++) {
        int row0 = m0 + wm * 64 + mi * 16 + (lane >> 2);
#pragma unroll
        for (int ni = 0; ni < 4; ni++) {
            int col = n0 + wn * 32 + ni * 8 + (lane & 3) * 2;
            *(float2*)(cz + (size_t)row0 * ldc + col) =
                make_float2(acc[mi][ni][0], acc[mi][ni][1]);
            *(float2*)(cz + (size_t)(row0 + 8) * ldc + col) =
                make_float2(acc[mi][ni][2], acc[mi][ni][3]);
        }
    }
}

// ---------------- rope q: fp32 qkv -> scaled, roped, bf16-split q ----------------
__global__ __launch_bounds__(256) void rope_q_kernel(
    const float* __restrict__ cosT, const float* __restrict__ sinT) {
    int idx = blockIdx.x * blockDim.x + threadIdx.x;  // NL*MT*H*32 threads
    int d = idx & 31;
    int h = (idx >> 5) & 15;
    int bt = (idx >> 9) & 2047;
    int l = idx >> 20;
    int t = bt & 1023;
    float c = cosT[t * 32 + d];
    float s = sinT[t * 32 + d];
    const float* p = g_qkv + ((size_t)l * MT_ + bt) * QKVW_ + h * HD_ + d;
    float x1 = p[0], x2 = p[32];
    float r1 = (x1 * c - x2 * s) * 0.125f;
    float r2 = (x2 * c + x1 * s) * 0.125f;
    size_t o = ((size_t)l * MT_ + bt) * D_ + h * HD_ + d;
    __nv_bfloat16 h1 = __float2bfloat16(r1);
    __nv_bfloat16 h2 = __float2bfloat16(r2);
    g_qh[o] = h1;       g_qh[o + 32] = h2;
    g_ql[o] = __float2bfloat16(r1 - __bfloat162float(h1));
    g_ql[o + 32] = __float2bfloat16(r2 - __bfloat162float(h2));
}

// ---------------- rope k + scatter bf16-split K/V caches ----------------
__global__ __launch_bounds__(256) void rope_kv_kernel(
    const float* __restrict__ cosT, const float* __restrict__ sinT) {
    int idx = blockIdx.x * blockDim.x + threadIdx.x;  // NL*MT*HKV*32 threads
    int d = idx & 31;
    int hkv = (idx >> 5) & 7;
    int bt = (idx >> 8) & 2047;
    int l = idx >> 19;
    int b = bt >> 10, t = bt & 1023;
    int pos = l * T_ + t;
    float c = cosT[pos * 32 + d];
    float s = sinT[pos * 32 + d];
    const float* row = g_qkv + ((size_t)l * MT_ + bt) * QKVW_;
    const float* kp = row + 1024 + hkv * HD_ + d;
    float k1 = kp[0], k2 = kp[32];
    float r1 = k1 * c - k2 * s;
    float r2 = k2 * c + k1 * s;
    size_t o = (((size_t)b * HKV_ + hkv) * MAXKV_ + pos) * HD_ + d;
    __nv_bfloat16 h1 = __float2bfloat16(r1);
    __nv_bfloat16 h2 = __float2bfloat16(r2);
    g_Kch[o] = h1;      g_Kch[o + 32] = h2;
    g_Kcl[o] = __float2bfloat16(r1 - __bfloat162float(h1));
    g_Kcl[o + 32] = __float2bfloat16(r2 - __bfloat162float(h2));
    float v1 = row[1536 + hkv * HD_ + d], v2 = row[1536 + hkv * HD_ + d + 32];
    __nv_bfloat16 vh1 = __float2bfloat16(v1);
    __nv_bfloat16 vh2 = __float2bfloat16(v2);
    g_Vch[o] = vh1;     g_Vch[o + 32] = vh2;
    g_Vcl[o] = __float2bfloat16(v1 - __bfloat162float(vh1));
    g_Vcl[o + 32] = __float2bfloat16(v2 - __bfloat162float(vh2));
}

// ---------------- tensor-core flash attention ----------------
// CTA: 128 thr / 4 warps. 128 q-rows x 64-kv chunks, HD=64.
// smem: Qh @0 (16KB), Ql @16KB; stage s @32KB + s*32KB: Kh,Kl,Vh,Vl (8KB each)
__global__ __launch_bounds__(128) void attn_tc() {
    extern __shared__ char sma[];
    const uint32_t sb = smem_u32(sma);
    const int tid = threadIdx.x, wid = tid >> 5, lane = tid & 31;
    const int l = 2 - (blockIdx.z >> 1), b = blockIdx.z & 1;   // heavy layers first
    const int h = blockIdx.y, hkv = h >> 1;
    const int t0 = blockIdx.x * 128;
    const int qbase = l * 1024 + t0;
    const int nfull = qbase >> 6;
    const int nch = nfull + 2;

    const __nv_bfloat16* qh = g_qh + ((size_t)(l * MT_ + b * T_ + t0)) * D_ + h * HD_;
    const __nv_bfloat16* ql = g_ql + ((size_t)(l * MT_ + b * T_ + t0)) * D_ + h * HD_;
    const size_t kvoff = ((size_t)b * HKV_ + hkv) * MAXKV_ * HD_;
    const __nv_bfloat16* kh = g_Kch + kvoff;
    const __nv_bfloat16* kl = g_Kcl + kvoff;
    const __nv_bfloat16* vh = g_Vch + kvoff;
    const __nv_bfloat16* vl = g_Vcl + kvoff;

    // load Q (rows stride D_ elements)
#pragma unroll
    for (int it = 0; it < 8; it++) {
        int idx = tid + it * 128;           // 1024 = 128 rows * 8 segs
        int r = idx >> 3, seg = idx & 7;
        uint32_t off = SWZ(r * 128 + seg * 16);
        cp_async16(sb + off, qh + (size_t)r * D_ + seg * 8);
        cp_async16(sb + 16384 + off, ql + (size_t)r * D_ + seg * 8);
    }
    // load chunk 0 into stage 0
    {
#pragma unroll
        for (int it = 0; it < 4; it++) {
            int idx = tid + it * 128;       // 512 = 64 rows * 8 segs
            int r = idx >> 3, seg = idx & 7;
            uint32_t off = SWZ(r * 128 + seg * 16);
            size_t go = (size_t)r * HD_ + seg * 8;
            cp_async16(sb + 32768 + off, kh + go);
            cp_async16(sb + 40960 + off, kl + go);
            cp_async16(sb + 49152 + off, vh + go);
            cp_async16(sb + 57344 + off, vl + go);
        }
    }
    cp_commit();

    float s[2][8][4], o[2][8][4], mrow[4], lrow[4];
#pragma unroll
    for (int i = 0; i < 4; i++) { mrow[i] = -1e30f; lrow[i] = 0.f; }
#pragma unroll
    for (int mi = 0; mi < 2; mi++)
#pragma unroll
        for (int nj = 0; nj < 8; nj++)
#pragma unroll
            for (int q = 0; q < 4; q++) o[mi][nj][q] = 0.f;

    const int r8 = lane & 7, mat = lane >> 3;

    for (int c = 0; c < nch; c++) {
        if (c + 1 < nch) {
            const uint32_t db = sb + 32768 + ((c + 1) & 1) * 32768;
#pragma unroll
            for (int it = 0; it < 4; it++) {
                int idx = tid + it * 128;
                int r = idx >> 3, seg = idx & 7;
                uint32_t off = SWZ(r * 128 + seg * 16);
                size_t go = ((size_t)(c + 1) * 64 + r) * HD_ + seg * 8;
                cp_async16(db + off, kh + go);
                cp_async16(db + 8192 + off, kl + go);
                cp_async16(db + 16384 + off, vh + go);
                cp_async16(db + 24576 + off, vl + go);
            }
            cp_commit();
            cp_wait1();
        } else {
            cp_wait0();
        }
        __syncthreads();
        const uint32_t kb_ = sb + 32768 + (c & 1) * 32768;

        // ---- S = Q * K^T ----
#pragma unroll
        for (int mi = 0; mi < 2; mi++)
#pragma unroll
            for (int nj = 0; nj < 8; nj++)
#pragma unroll
                for (int q = 0; q < 4; q++) s[mi][nj][q] = 0.f;

#pragma unroll
        for (int ks = 0; ks < 4; ks++) {
            uint32_t bh[8][2], bl[8][2];
#pragma unroll
            for (int p = 0; p < 4; p++) {
                uint32_t nrow = p * 16 + (lane >> 4) * 8 + r8;
                uint32_t nbyte = ks * 32 + ((lane >> 3) & 1) * 16;
                uint32_t off = SWZ(nrow * 128 + nbyte);
                uint32_t th[4], tl[4];
                ldm_x4(th, kb_ + off);
                ldm_x4(tl, kb_ + 8192 + off);
                bh[2 * p][0] = th[0]; bh[2 * p][1] = th[1];
                bh[2 * p + 1][0] = th[2]; bh[2 * p + 1][1] = th[3];
                bl[2 * p][0] = tl[0]; bl[2 * p][1] = tl[1];
                bl[2 * p + 1][0] = tl[2]; bl[2 * p + 1][1] = tl[3];
            }
#pragma unroll
            for (int mi = 0; mi < 2; mi++) {
                uint32_t arow = wid * 32 + mi * 16 + r8 + (mat & 1) * 8;
                uint32_t abyte = ks * 32 + (mat >> 1) * 16;
                uint32_t off = SWZ(arow * 128 + abyte);
                uint32_t ahi[4], alo[4];
                ldm_x4(ahi, sb + off);
                ldm_x4(alo, sb + 16384 + off);
#pragma unroll
                for (int nj = 0; nj < 8; nj++) {
                    mma16816(s[mi][nj], ahi, bh[nj]);
                    mma16816(s[mi][nj], ahi, bl[nj]);
                    mma16816(s[mi][nj], alo, bh[nj]);
                }
            }
        }

        // ---- causal mask (last two chunks) ----
        if (c >= nfull) {
            int rel = (c - nfull) * 64;
#pragma unroll
            for (int mi = 0; mi < 2; mi++) {
                int rbase = wid * 32 + mi * 16 + (lane >> 2);
#pragma unroll
                for (int nj = 0; nj < 8; nj++) {
                    int cbase = nj * 8 + (lane & 3) * 2 + rel;
#pragma unroll
                    for (int q = 0; q < 4; q++) {
                        int rr = rbase + (q >> 1) * 8;
                        int cc = cbase + (q & 1);
                        if (cc > rr) s[mi][nj][q] = -1e30f;
                    }
                }
            }
        }

        // ---- online softmax ----
#pragma unroll
        for (int mi = 0; mi < 2; mi++)
#pragma unroll
            for (int half = 0; half < 2; half++) {
                int ix = mi * 2 + half;
                float mx = -1e30f;
#pragma unroll
                for (int nj = 0; nj < 8; nj++) {
                    mx = fmaxf(mx, s[mi][nj][half * 2]);
                    mx = fmaxf(mx, s[mi][nj][half * 2 + 1]);
                }
                mx = fmaxf(mx, __shfl_xor_sync(0xffffffffu, mx, 1));
                mx = fmaxf(mx, __shfl_xor_sync(0xffffffffu, mx, 2));
                float mn = fmaxf(mrow[ix], mx);
                float fac = __expf(mrow[ix] - mn);
                mrow[ix] = mn;
                float ps = 0.f;
#pragma unroll
                for (int nj = 0; nj < 8; nj++) {
                    float p0 = __expf(s[mi][nj][half * 2] - mn);
                    float p1 = __expf(s[mi][nj][half * 2 + 1] - mn);
                    s[mi][nj][half * 2] = p0;
                    s[mi][nj][half * 2 + 1] = p1;
                    ps += p0 + p1;
                    o[mi][nj][half * 2] *= fac;
                    o[mi][nj][half * 2 + 1] *= fac;
                }
                ps += __shfl_xor_sync(0xffffffffu, ps, 1);
                ps += __shfl_xor_sync(0xffffffffu, ps, 2);
                lrow[ix] = lrow[ix] * fac + ps;
            }

        // ---- O += P * V ----
#pragma unroll
        for (int kb = 0; kb < 4; kb++) {
            // P fragments straight from accumulators (C layout == A layout)
            uint32_t phi[2][4], plo[2][4];
#pragma unroll
            for (int mi = 0; mi < 2; mi++) {
#pragma unroll
                for (int half2 = 0; half2 < 2; half2++) {   // a0/a1 from nj=2kb, a2/a3 from 2kb+1
                    int nj = 2 * kb + half2;
#pragma unroll
                    for (int rh = 0; rh < 2; rh++) {
                        float p0 = s[mi][nj][rh * 2], p1 = s[mi][nj][rh * 2 + 1];
                        uint32_t u0 = __float_as_uint(p0), u1 = __float_as_uint(p1);
                        uint32_t hpack = __byte_perm(u0, u1, 0x7632);   // exact bf16 truncation
                        float l0 = p0 - __uint_as_float(u0 & 0xFFFF0000u);
                        float l1 = p1 - __uint_as_float(u1 & 0xFFFF0000u);
                        __nv_bfloat162 lp = __floats2bfloat162_rn(l0, l1);
                        phi[mi][half2 * 2 + rh] = hpack;
                        plo[mi][half2 * 2 + rh] = *(uint32_t*)&lp;
                    }
                }
            }
            uint32_t bvh[8][2], bvl[8][2];
#pragma unroll
            for (int p = 0; p < 4; p++) {   // n-tile pair (2p, 2p+1) of HD
                uint32_t krow = kb * 16 + ((lane >> 3) & 1) * 8 + r8;
                uint32_t nbyte = (2 * p + (lane >> 4)) * 16;
                uint32_t off = SWZ(krow * 128 + nbyte);
                uint32_t th[4], tl[4];
                ldm_x4t(th, kb_ + 16384 + off);
                ldm_x4t(tl, kb_ + 24576 + off);
                bvh[2 * p][0] = th[0]; bvh[2 * p][1] = th[1];
                bvh[2 * p + 1][0] = th[2]; bvh[2 * p + 1][1] = th[3];
                bvl[2 * p][0] = tl[0]; bvl[2 * p][1] = tl[1];
                bvl[2 * p + 1][0] = tl[2]; bvl[2 * p + 1][1] = tl[3];
            }
#pragma unroll
            for (int mi = 0; mi < 2; mi++)
#pragma unroll
                for (int nj = 0; nj < 8; nj++) {
                    mma16816(o[mi][nj], phi[mi], bvh[nj]);
                    mma16816(o[mi][nj], phi[mi], bvl[nj]);
                    mma16816(o[mi][nj], plo[mi], bvh[nj]);
                }
        }
        __syncthreads();
    }

    // ---- epilogue ----
    float inv[4];
#pragma unroll
    for (int i = 0; i < 4; i++) inv[i] = 1.f / lrow[i];
    float* ob = g_o + ((size_t)(l * MT_ + b * T_ + t0)) * D_ + h * HD_;
#pragma unroll
    for (int mi = 0; mi < 2; mi++)
#pragma unroll
        for (int half = 0; half < 2; half++) {
            int row = wid * 32 + mi * 16 + (lane >> 2) + half * 8;
            float iv = inv[mi * 2 + half];
            float* op = ob + (size_t)row * D_ + (lane & 3) * 2;
#pragma unroll
            for (int nj = 0; nj < 8; nj++)
                *(float2*)(op + nj * 8) =
                    make_float2(o[mi][nj][half * 2] * iv, o[mi][nj][half * 2 + 1] * iv);
        }
}

// ---------------- combine -> bf16-split y ----------------
__device__ __forceinline__ float blk_sum(float v, float* sred) {
#pragma unroll
    for (int off = 16; off; off >>= 1) v += __shfl_xor_sync(0xffffffffu, v, off);
    int w = threadIdx.x >> 5;
    if ((threadIdx.x & 31) == 0) sred[w] = v;
    __syncthreads();
    if (threadIdx.x < 32) {
        float t = (threadIdx.x < 8) ? sred[threadIdx.x] : 0.f;
#pragma unroll
        for (int off = 4; off; off >>= 1) t += __shfl_xor_sync(0xffffffffu, t, off);
        if (threadIdx.x == 0) sred[8] = t;
    }
    __syncthreads();
    return sred[8];
}

__global__ __launch_bounds__(256) void combine_kernel(
    const float* __restrict__ x, const float* __restrict__ ln_w,
    const float* __restrict__ final_ln_w, const float* __restrict__ alpha) {
    __shared__ float sred[9];
    const int row = blockIdx.x;
    const int d = threadIdx.x * 4;
    float4 a[NL_];
    float rl[NL_];
#pragma unroll
    for (int l2 = 0; l2 < NL_; l2++)
        a[l2] = *(const float4*)(g_o + ((size_t)l2 * MT_ + row) * D_ + d);
#pragma unroll
    for (int l2 = 0; l2 < NL_; l2++) {
        float s = a[l2].x * a[l2].x + a[l2].y * a[l2].y +
                  a[l2].z * a[l2].z + a[l2].w * a[l2].w;
        float tot = blk_sum(s, sred);
        rl[l2] = rsqrtf(tot * (1.f / D_) + EPS_) * g_lw[l2];
    }
    float4 xv = *(const float4*)(x + (size_t)row * D_ + d);
    float al = alpha[0];
    float4 acc = make_float4(al * xv.x, al * xv.y, al * xv.z, al * xv.w);
#pragma unroll
    for (int l2 = 0; l2 < NL_; l2++) {
        float4 w = *(const float4*)(ln_w + l2 * D_ + d);
        acc.x += a[l2].x * rl[l2] * w.x;
        acc.y += a[l2].y * rl[l2] * w.y;
        acc.z += a[l2].z * rl[l2] * w.z;
        acc.w += a[l2].w * rl[l2] * w.w;
    }
    float s2 = acc.x * acc.x + acc.y * acc.y + acc.z * acc.z + acc.w * acc.w;
    float rf = rsqrtf(blk_sum(s2, sred) * (1.f / D_) + EPS_);
    float4 fw = *(const float4*)(final_ln_w + d);
    float outv[4] = {acc.x * rf * fw.x, acc.y * rf * fw.y,
                     acc.z * rf * fw.z, acc.w * rf * fw.w};
    size_t base = (size_t)row * D_ + d;
#pragma unroll
    for (int j = 0; j < 4; j++) {
        __nv_bfloat16 h = __float2bfloat16(outv[j]);
        g_yhi[base + j] = h;
        g_ylo[base + j] = __float2bfloat16(outv[j] - __bfloat162float(h));
    }
}

// ---------------- launch ----------------
extern "C" void kernel_launch(void* const* d_in, const int* in_sizes, int n_in,
                              void* d_out, int out_size) {
    const float* x          = (const float*)d_in[0];
    const float* cosT       = (const float*)d_in[1];
    const float* sinT       = (const float*)d_in[2];
    const float* q_w        = (const float*)d_in[3];
    const float* k_w        = (const float*)d_in[4];
    const float* v_w        = (const float*)d_in[5];
    const float* ln_w       = (const float*)d_in[6];
    const float* lam        = (const float*)d_in[7];
    const float* out_w      = (const float*)d_in[8];
    const float* final_ln_w = (const float*)d_in[9];
    const float* alpha      = (const float*)d_in[10];

    __nv_bfloat16 *p_xhi, *p_xlo, *p_wqh, *p_wql, *p_woh, *p_wol, *p_yh, *p_yl;
    float* p_qkv;
    cudaGetSymbolAddress((void**)&p_xhi, g_xhi);
    cudaGetSymbolAddress((void**)&p_xlo, g_xlo);
    cudaGetSymbolAddress((void**)&p_wqh, g_wqkv_hi);
    cudaGetSymbolAddress((void**)&p_wql, g_wqkv_lo);
    cudaGetSymbolAddress((void**)&p_woh, g_wo_hi);
    cudaGetSymbolAddress((void**)&p_wol, g_wo_lo);
    cudaGetSymbolAddress((void**)&p_yh, g_yhi);
    cudaGetSymbolAddress((void**)&p_yl, g_ylo);
    cudaGetSymbolAddress((void**)&p_qkv, g_qkv);

    cudaFuncSetAttribute(gemm_tc, cudaFuncAttributeMaxDynamicSharedMemorySize, GSMEM);
    cudaFuncSetAttribute(attn_tc, cudaFuncAttributeMaxDynamicSharedMemorySize, ASMEM);

    k_prep<<<1, 32>>>(lam);
    split_f32<<<(MT_ * D_) / 256, 256>>>(x, p_xhi, p_xlo);
    pack_wqkv<<<(NL_ * QKVW_ * D_) / 256, 256>>>(q_w, k_w, v_w);
    split_f32<<<(D_ * D_) / 256, 256>>>(out_w, p_woh, p_wol);

    gemm_tc<<<dim3(16, 16, 3), 256, GSMEM>>>(p_xhi, p_xlo, p_wqh, p_wql,
                                             p_qkv, QKVW_, QKVW_,
                                             (long)MT_ * QKVW_);

    rope_q_kernel<<<(NL_ * MT_ * H_ * 32) / 256, 256>>>(cosT, sinT);
    rope_kv_kernel<<<(NL_ * MT_ * HKV_ * 32) / 256, 256>>>(cosT, sinT);
    attn_tc<<<dim3(8, 16, NL_ * B_), 128, ASMEM>>>();
    combine_kernel<<<MT_, 256>>>(x, ln_w, final_ln_w, alpha);

    gemm_tc<<<dim3(8, 16, 1), 256, GSMEM>>>(p_yh, p_yl, p_woh, p_wol,
                                            (float*)d_out, D_, D_, 0L);
}

// round 7
// speedup vs baseline: 7.2468x; 1.2566x over previous
#include <cuda_runtime.h>
#include <cuda_bf16.h>
#include <cuda_fp16.h>
#include <math.h>
#include <stdint.h>

#define B_ 2
#define T_ 1024
#define D_ 1024
#define H_ 16
#define HKV_ 8
#define HD_ 64
#define NL_ 3
#define MAXKV_ 3072
#define MT_ 2048
#define EPS_ 1e-5f
#define QKVW_ 2048
#define GSMEM (2 * 4 * 16384)              // gemm: 2 stages x 4 matrices x 16KB
#define ASMEM (32768 + 2 * 24576)          // attn: Q hi/lo 32KB + 2 stages x (K,Vh,Vl) 24KB

// ---------------- scratch ----------------
__device__ __align__(256) float g_qkv[NL_ * MT_ * QKVW_];
__device__ __align__(256) float g_o[NL_ * MT_ * D_];
__device__ __align__(256) __half g_qh[NL_ * MT_ * D_];
__device__ __align__(256) __half g_ql[NL_ * MT_ * D_];
__device__ __align__(256) __half g_Kc[B_ * HKV_ * MAXKV_ * HD_];
__device__ __align__(256) __half g_Vh[B_ * HKV_ * MAXKV_ * HD_];
__device__ __align__(256) __half g_Vl[B_ * HKV_ * MAXKV_ * HD_];
__device__ __align__(256) __nv_bfloat16 g_xhi[MT_ * D_];
__device__ __align__(256) __nv_bfloat16 g_xlo[MT_ * D_];
__device__ __align__(256) __nv_bfloat16 g_wqkv_hi[NL_ * QKVW_ * D_];
__device__ __align__(256) __nv_bfloat16 g_wqkv_lo[NL_ * QKVW_ * D_];
__device__ __align__(256) __nv_bfloat16 g_wo_hi[D_ * D_];
__device__ __align__(256) __nv_bfloat16 g_wo_lo[D_ * D_];
__device__ __align__(256) __nv_bfloat16 g_yhi[MT_ * D_];
__device__ __align__(256) __nv_bfloat16 g_ylo[MT_ * D_];
__device__ float g_lw[NL_];

// ---------------- helpers ----------------
__device__ __forceinline__ uint32_t smem_u32(const void* p) {
    uint32_t a;
    asm("{ .reg .u64 t; cvta.to.shared.u64 t, %1; cvt.u32.u64 %0, t; }" : "=r"(a) : "l"(p));
    return a;
}
__device__ __forceinline__ void cp_async16(uint32_t dst, const void* src) {
    asm volatile("cp.async.cg.shared.global [%0], [%1], 16;\n" :: "r"(dst), "l"(src));
}
__device__ __forceinline__ void cp_commit() { asm volatile("cp.async.commit_group;\n"); }
__device__ __forceinline__ void cp_wait1() { asm volatile("cp.async.wait_group 1;\n" ::: "memory"); }
__device__ __forceinline__ void cp_wait0() { asm volatile("cp.async.wait_group 0;\n" ::: "memory"); }

__device__ __forceinline__ void ldm_x4(uint32_t* r, uint32_t addr) {
    asm volatile("ldmatrix.sync.aligned.m8n8.x4.shared.b16 {%0,%1,%2,%3}, [%4];"
                 : "=r"(r[0]), "=r"(r[1]), "=r"(r[2]), "=r"(r[3]) : "r"(addr));
}
__device__ __forceinline__ void ldm_x4t(uint32_t* r, uint32_t addr) {
    asm volatile("ldmatrix.sync.aligned.m8n8.x4.trans.shared.b16 {%0,%1,%2,%3}, [%4];"
                 : "=r"(r[0]), "=r"(r[1]), "=r"(r[2]), "=r"(r[3]) : "r"(addr));
}
__device__ __forceinline__ void ldm_x2(uint32_t* r, uint32_t addr) {
    asm volatile("ldmatrix.sync.aligned.m8n8.x2.shared.b16 {%0,%1}, [%2];"
                 : "=r"(r[0]), "=r"(r[1]) : "r"(addr));
}
__device__ __forceinline__ void mma_bf16(float* c, const uint32_t* a, const uint32_t* b) {
    asm volatile(
        "mma.sync.aligned.m16n8k16.row.col.f32.bf16.bf16.f32 "
        "{%0,%1,%2,%3}, {%4,%5,%6,%7}, {%8,%9}, {%0,%1,%2,%3};"
        : "+f"(c[0]), "+f"(c[1]), "+f"(c[2]), "+f"(c[3])
        : "r"(a[0]), "r"(a[1]), "r"(a[2]), "r"(a[3]), "r"(b[0]), "r"(b[1]));
}
__device__ __forceinline__ void mma_f16(float* c, const uint32_t* a, const uint32_t* b) {
    asm volatile(
        "mma.sync.aligned.m16n8k16.row.col.f32.f16.f16.f32 "
        "{%0,%1,%2,%3}, {%4,%5,%6,%7}, {%8,%9}, {%0,%1,%2,%3};"
        : "+f"(c[0]), "+f"(c[1]), "+f"(c[2]), "+f"(c[3])
        : "r"(a[0]), "r"(a[1]), "r"(a[2]), "r"(a[3]), "r"(b[0]), "r"(b[1]));
}
#define SWZ(x) ((x) ^ (((x) >> 3) & 0x70))

// ---------------- lambda prep ----------------
__global__ void k_prep(const float* __restrict__ lam) {
    if (threadIdx.x == 0) {
        float s0 = 1.f / (1.f + expf(-lam[0]));
        float s1 = 1.f / (1.f + expf(-lam[1]));
        float s2 = 1.f / (1.f + expf(-lam[2]));
        float mean = (s0 + s1 + s2) * (1.f / 3.f);
        float var = ((s0 - mean) * (s0 - mean) + (s1 - mean) * (s1 - mean) +
                     (s2 - mean) * (s2 - mean)) * (1.f / 3.f);
        float r = rsqrtf(var + EPS_);
        g_lw[0] = (s0 - mean) * r;
        g_lw[1] = (s1 - mean) * r;
        g_lw[2] = (s2 - mean) * r;
    }
}

// ---------------- vectorized bf16 split preps ----------------
__device__ __forceinline__ uint32_t pack_bf16_pair(float a, float b,
                                                   float* ra, float* rb) {
    __nv_bfloat16 ha = __float2bfloat16(a);
    __nv_bfloat16 hb = __float2bfloat16(b);
    *ra = a - __bfloat162float(ha);
    *rb = b - __bfloat162float(hb);
    __nv_bfloat162 p = {ha, hb};
    return *(uint32_t*)&p;
}

__global__ __launch_bounds__(256) void split_f32_v4(const float* __restrict__ src,
                                                    __nv_bfloat16* __restrict__ hi,
                                                    __nv_bfloat16* __restrict__ lo) {
    int i = (blockIdx.x * 256 + threadIdx.x) * 4;
    float4 f = *(const float4*)(src + i);
    float rx, ry, rz, rw;
    uint32_t h0 = pack_bf16_pair(f.x, f.y, &rx, &ry);
    uint32_t h1 = pack_bf16_pair(f.z, f.w, &rz, &rw);
    __nv_bfloat162 l0 = __floats2bfloat162_rn(rx, ry);
    __nv_bfloat162 l1 = __floats2bfloat162_rn(rz, rw);
    *(uint2*)(hi + i) = make_uint2(h0, h1);
    *(uint2*)(lo + i) = make_uint2(*(uint32_t*)&l0, *(uint32_t*)&l1);
}

__global__ __launch_bounds__(256) void pack_wqkv_v4(const float* __restrict__ q_w,
                                                    const float* __restrict__ k_w,
                                                    const float* __restrict__ v_w) {
    int i = (blockIdx.x * 256 + threadIdx.x) * 4;   // 3*2048*1024 total
    int kk = i & 1023;
    int r = (i >> 10) & 2047;
    int l = i >> 21;
    const float* src;
    if (r < 1024)       src = q_w + (size_t)l * 1048576 + (size_t)r * 1024 + kk;
    else if (r < 1536)  src = k_w + (size_t)l * 524288 + (size_t)(r - 1024) * 1024 + kk;
    else                src = v_w + (size_t)l * 524288 + (size_t)(r - 1536) * 1024 + kk;
    float4 f = *(const float4*)src;
    float rx, ry, rz, rw;
    uint32_t h0 = pack_bf16_pair(f.x, f.y, &rx, &ry);
    uint32_t h1 = pack_bf16_pair(f.z, f.w, &rz, &rw);
    __nv_bfloat162 l0 = __floats2bfloat162_rn(rx, ry);
    __nv_bfloat162 l1 = __floats2bfloat162_rn(rz, rw);
    *(uint2*)(g_wqkv_hi + i) = make_uint2(h0, h1);
    *(uint2*)(g_wqkv_lo + i) = make_uint2(*(uint32_t*)&l0, *(uint32_t*)&l1);
}

// ---------------- bf16x3 tensor-core GEMM ----------------
__global__ __launch_bounds__(256, 1) void gemm_tc(
    const __nv_bfloat16* __restrict__ Ahi, const __nv_bfloat16* __restrict__ Alo,
    const __nv_bfloat16* __restrict__ Bhi, const __nv_bfloat16* __restrict__ Blo,
    float* __restrict__ C, int bRows, int ldc, long strideC) {
    extern __shared__ char sm[];
    const uint32_t sb = smem_u32(sm);
    const int tid = threadIdx.x;
    const int wid = tid >> 5, lane = tid & 31;
    const int wm = wid & 1, wn = wid >> 1;
    const int n0 = blockIdx.x * 128, m0 = blockIdx.y * 128, z = blockIdx.z;
    const int K = 1024, NK = 16;

    const __nv_bfloat16* srcp[4] = {
        Ahi + (size_t)m0 * K, Alo + (size_t)m0 * K,
        Bhi + ((size_t)z * bRows + n0) * K, Blo + ((size_t)z * bRows + n0) * K};

#pragma unroll
    for (int it = 0; it < 16; it++) {
        int idx = tid + it * 256;
        int t = idx >> 10, row = (idx >> 3) & 127, seg = idx & 7;
        cp_async16(sb + t * 16384 + SWZ(row * 128 + seg * 16),
                   srcp[t] + (size_t)row * K + seg * 8);
    }
    cp_commit();

    float acc[4][4][4];
#pragma unroll
    for (int mi = 0; mi < 4; mi++)
#pragma unroll
        for (int ni = 0; ni < 4; ni++)
#pragma unroll
            for (int q = 0; q < 4; q++) acc[mi][ni][q] = 0.f;

    const int r8 = lane & 7, mat = lane >> 3;
    const int lb = lane & 15, matb = lb >> 3, r8b = lb & 7;

    for (int kc = 0; kc < NK; kc++) {
        const uint32_t cb = sb + (kc & 1) * 65536;
        if (kc + 1 < NK) {
            const uint32_t db = sb + ((kc + 1) & 1) * 65536;
            const int ko = (kc + 1) * 64;
#pragma unroll
            for (int it = 0; it < 16; it++) {
                int idx = tid + it * 256;
                int t = idx >> 10, row = (idx >> 3) & 127, seg = idx & 7;
                cp_async16(db + t * 16384 + SWZ(row * 128 + seg * 16),
                           srcp[t] + (size_t)row * K + ko + seg * 8);
            }
            cp_commit();
            cp_wait1();
        } else {
            cp_wait0();
        }
        __syncthreads();

#pragma unroll
        for (int ks = 0; ks < 4; ks++) {
            uint32_t bhi[4][2], blo[4][2];
#pragma unroll
            for (int ni = 0; ni < 4; ni++) {
                uint32_t brow = wn * 32 + ni * 8 + r8b;
                uint32_t bbyte = ks * 32 + matb * 16;
                uint32_t off = SWZ(brow * 128 + bbyte);
                ldm_x2(bhi[ni], cb + 32768 + off);
                ldm_x2(blo[ni], cb + 49152 + off);
            }
#pragma unroll
            for (int mi = 0; mi < 4; mi++) {
                uint32_t arow = wm * 64 + mi * 16 + r8 + (mat & 1) * 8;
                uint32_t abyte = ks * 32 + (mat >> 1) * 16;
                uint32_t off = SWZ(arow * 128 + abyte);
                uint32_t ahi[4], alo[4];
                ldm_x4(ahi, cb + off);
                ldm_x4(alo, cb + 16384 + off);
#pragma unroll
                for (int ni = 0; ni < 4; ni++) {
                    mma_bf16(acc[mi][ni], ahi, bhi[ni]);
                    mma_bf16(acc[mi][ni], ahi, blo[ni]);
                    mma_bf16(acc[mi][ni], alo, bhi[ni]);
                }
            }
        }
        __syncthreads();
    }

    float* cz = C + (size_t)z * strideC;
#pragma unroll
    for (int mi = 0; mi < 4; mi++) {
        int row0 = m0 + wm * 64 + mi * 16 + (lane >> 2);
#pragma unroll
        for (int ni = 0; ni < 4; ni++) {
            int col = n0 + wn * 32 + ni * 8 + (lane & 3) * 2;
            *(float2*)(cz + (size_t)row0 * ldc + col) =
                make_float2(acc[mi][ni][0], acc[mi][ni][1]);
            *(float2*)(cz + (size_t)(row0 + 8) * ldc + col) =
                make_float2(acc[mi][ni][2], acc[mi][ni][3]);
        }
    }
}

// ---------------- rope q: fp32 qkv -> scaled, roped, fp16-split q ----------------
__global__ __launch_bounds__(256) void rope_q_kernel(
    const float* __restrict__ cosT, const float* __restrict__ sinT) {
    int idx = blockIdx.x * blockDim.x + threadIdx.x;  // NL*MT*H*32 threads
    int d = idx & 31;
    int h = (idx >> 5) & 15;
    int bt = (idx >> 9) & 2047;
    int l = idx >> 20;
    int t = bt & 1023;
    float c = cosT[t * 32 + d];
    float s = sinT[t * 32 + d];
    const float* p = g_qkv + ((size_t)l * MT_ + bt) * QKVW_ + h * HD_ + d;
    float x1 = p[0], x2 = p[32];
    float r1 = (x1 * c - x2 * s) * 0.125f;
    float r2 = (x2 * c + x1 * s) * 0.125f;
    size_t o = ((size_t)l * MT_ + bt) * D_ + h * HD_ + d;
    __half h1 = __float2half(r1);
    __half h2 = __float2half(r2);
    g_qh[o] = h1;       g_qh[o + 32] = h2;
    g_ql[o] = __float2half(r1 - __half2float(h1));
    g_ql[o + 32] = __float2half(r2 - __half2float(h2));
}

// ---------------- rope k + scatter fp16 K (single) / V (split) caches ----------------
__global__ __launch_bounds__(256) void rope_kv_kernel(
    const float* __restrict__ cosT, const float* __restrict__ sinT) {
    int idx = blockIdx.x * blockDim.x + threadIdx.x;  // NL*MT*HKV*32 threads
    int d = idx & 31;
    int hkv = (idx >> 5) & 7;
    int bt = (idx >> 8) & 2047;
    int l = idx >> 19;
    int b = bt >> 10, t = bt & 1023;
    int pos = l * T_ + t;
    float c = cosT[pos * 32 + d];
    float s = sinT[pos * 32 + d];
    const float* row = g_qkv + ((size_t)l * MT_ + bt) * QKVW_;
    const float* kp = row + 1024 + hkv * HD_ + d;
    float k1 = kp[0], k2 = kp[32];
    size_t o = (((size_t)b * HKV_ + hkv) * MAXKV_ + pos) * HD_ + d;
    g_Kc[o]      = __float2half(k1 * c - k2 * s);
    g_Kc[o + 32] = __float2half(k2 * c + k1 * s);
    float v1 = row[1536 + hkv * HD_ + d], v2 = row[1536 + hkv * HD_ + d + 32];
    __half vh1 = __float2half(v1);
    __half vh2 = __float2half(v2);
    g_Vh[o] = vh1;      g_Vh[o + 32] = vh2;
    g_Vl[o] = __float2half(v1 - __half2float(vh1));
    g_Vl[o + 32] = __float2half(v2 - __half2float(vh2));
}

// ---------------- fp16 tensor-core flash attention (4 MMAs per S/PV pair) ----------------
// CTA: 128 thr / 4 warps. 128 q-rows x 64-kv chunks, HD=64.
// smem: Qh @0 (16KB), Ql @16KB; stage s @32KB + s*24KB: K(8KB), Vh(8KB), Vl(8KB)
// grid: (32 inst, 24 ranked combos) — heavy (layer,tile) first.
__global__ __launch_bounds__(128) void attn_tc() {
    extern __shared__ char sma[];
    const uint32_t sb = smem_u32(sma);
    const int tid = threadIdx.x, wid = tid >> 5, lane = tid & 31;
    const int rank = blockIdx.y;
    const int l = 2 - (rank >> 3), tile = 7 - (rank & 7);
    const int b = blockIdx.x & 1, h = blockIdx.x >> 1, hkv = h >> 1;
    const int t0 = tile * 128;
    const int nfull = l * 16 + tile * 2;
    const int nch = nfull + 2;

    const __half* qh = g_qh + ((size_t)(l * MT_ + b * T_ + t0)) * D_ + h * HD_;
    const __half* ql = g_ql + ((size_t)(l * MT_ + b * T_ + t0)) * D_ + h * HD_;
    const size_t kvoff = ((size_t)b * HKV_ + hkv) * MAXKV_ * HD_;
    const __half* kc = g_Kc + kvoff;
    const __half* vh = g_Vh + kvoff;
    const __half* vl = g_Vl + kvoff;

    // load Q hi/lo (128 rows x 64 fp16 = 128B rows)
#pragma unroll
    for (int it = 0; it < 8; it++) {
        int idx = tid + it * 128;           // 1024 = 128 rows * 8 segs
        int r = idx >> 3, seg = idx & 7;
        uint32_t off = SWZ(r * 128 + seg * 16);
        cp_async16(sb + off, qh + (size_t)r * D_ + seg * 8);
        cp_async16(sb + 16384 + off, ql + (size_t)r * D_ + seg * 8);
    }
    // load chunk 0 into stage 0
#pragma unroll
    for (int it = 0; it < 4; it++) {
        int idx = tid + it * 128;           // 512 = 64 rows * 8 segs
        int r = idx >> 3, seg = idx & 7;
        uint32_t off = SWZ(r * 128 + seg * 16);
        size_t go = (size_t)r * HD_ + seg * 8;
        cp_async16(sb + 32768 + off, kc + go);
        cp_async16(sb + 40960 + off, vh + go);
        cp_async16(sb + 49152 + off, vl + go);
    }
    cp_commit();

    float s[2][8][4], o[2][8][4], mrow[4], lrow[4];
#pragma unroll
    for (int i = 0; i < 4; i++) { mrow[i] = -1e30f; lrow[i] = 0.f; }
#pragma unroll
    for (int mi = 0; mi < 2; mi++)
#pragma unroll
        for (int nj = 0; nj < 8; nj++)
#pragma unroll
            for (int q = 0; q < 4; q++) o[mi][nj][q] = 0.f;

    const int r8 = lane & 7, mat = lane >> 3;

    for (int c = 0; c < nch; c++) {
        if (c + 1 < nch) {
            const uint32_t db = sb + 32768 + ((c + 1) & 1) * 24576;
#pragma unroll
            for (int it = 0; it < 4; it++) {
                int idx = tid + it * 128;
                int r = idx >> 3, seg = idx & 7;
                uint32_t off = SWZ(r * 128 + seg * 16);
                size_t go = ((size_t)(c + 1) * 64 + r) * HD_ + seg * 8;
                cp_async16(db + off, kc + go);
                cp_async16(db + 8192 + off, vh + go);
                cp_async16(db + 16384 + off, vl + go);
            }
            cp_commit();
            cp_wait1();
        } else {
            cp_wait0();
        }
        __syncthreads();
        const uint32_t kb_ = sb + 32768 + (c & 1) * 24576;

        // ---- S = (Qhi + Qlo) * K^T : 2 MMAs per tile ----
#pragma unroll
        for (int mi = 0; mi < 2; mi++)
#pragma unroll
            for (int nj = 0; nj < 8; nj++)
#pragma unroll
                for (int q = 0; q < 4; q++) s[mi][nj][q] = 0.f;

#pragma unroll
        for (int ks = 0; ks < 4; ks++) {
            uint32_t bh[8][2];
#pragma unroll
            for (int p = 0; p < 4; p++) {
                uint32_t nrow = p * 16 + (lane >> 4) * 8 + r8;
                uint32_t nbyte = ks * 32 + ((lane >> 3) & 1) * 16;
                uint32_t off = SWZ(nrow * 128 + nbyte);
                uint32_t th[4];
                ldm_x4(th, kb_ + off);
                bh[2 * p][0] = th[0]; bh[2 * p][1] = th[1];
                bh[2 * p + 1][0] = th[2]; bh[2 * p + 1][1] = th[3];
            }
#pragma unroll
            for (int mi = 0; mi < 2; mi++) {
                uint32_t arow = wid * 32 + mi * 16 + r8 + (mat & 1) * 8;
                uint32_t abyte = ks * 32 + (mat >> 1) * 16;
                uint32_t off = SWZ(arow * 128 + abyte);
                uint32_t ahi[4], alo[4];
                ldm_x4(ahi, sb + off);
                ldm_x4(alo, sb + 16384 + off);
#pragma unroll
                for (int nj = 0; nj < 8; nj++) {
                    mma_f16(s[mi][nj], ahi, bh[nj]);
                    mma_f16(s[mi][nj], alo, bh[nj]);
                }
            }
        }

        // ---- causal mask (last two chunks) ----
        if (c >= nfull) {
            int rel = (c - nfull) * 64;
#pragma unroll
            for (int mi = 0; mi < 2; mi++) {
                int rbase = wid * 32 + mi * 16 + (lane >> 2);
#pragma unroll
                for (int nj = 0; nj < 8; nj++) {
                    int cbase = nj * 8 + (lane & 3) * 2 + rel;
#pragma unroll
                    for (int q = 0; q < 4; q++) {
                        int rr = rbase + (q >> 1) * 8;
                        int cc = cbase + (q & 1);
                        if (cc > rr) s[mi][nj][q] = -1e30f;
                    }
                }
            }
        }

        // ---- online softmax ----
#pragma unroll
        for (int mi = 0; mi < 2; mi++)
#pragma unroll
            for (int half = 0; half < 2; half++) {
                int ix = mi * 2 + half;
                float mx = -1e30f;
#pragma unroll
                for (int nj = 0; nj < 8; nj++) {
                    mx = fmaxf(mx, s[mi][nj][half * 2]);
                    mx = fmaxf(mx, s[mi][nj][half * 2 + 1]);
                }
                mx = fmaxf(mx, __shfl_xor_sync(0xffffffffu, mx, 1));
                mx = fmaxf(mx, __shfl_xor_sync(0xffffffffu, mx, 2));
                float mn = fmaxf(mrow[ix], mx);
                float fac = __expf(mrow[ix] - mn);
                mrow[ix] = mn;
                float ps = 0.f;
#pragma unroll
                for (int nj = 0; nj < 8; nj++) {
                    float p0 = __expf(s[mi][nj][half * 2] - mn);
                    float p1 = __expf(s[mi][nj][half * 2 + 1] - mn);
                    s[mi][nj][half * 2] = p0;
                    s[mi][nj][half * 2 + 1] = p1;
                    ps += p0 + p1;
                    o[mi][nj][half * 2] *= fac;
                    o[mi][nj][half * 2 + 1] *= fac;
                }
                ps += __shfl_xor_sync(0xffffffffu, ps, 1);
                ps += __shfl_xor_sync(0xffffffffu, ps, 2);
                lrow[ix] = lrow[ix] * fac + ps;
            }

        // ---- O += P * (Vhi + Vlo) : 2 MMAs per tile ----
#pragma unroll
        for (int kb = 0; kb < 4; kb++) {
            uint32_t pfr[2][4];
#pragma unroll
            for (int mi = 0; mi < 2; mi++)
#pragma unroll
                for (int half2 = 0; half2 < 2; half2++) {
                    int nj = 2 * kb + half2;
#pragma unroll
                    for (int rh = 0; rh < 2; rh++) {
                        __half2 hp = __floats2half2_rn(s[mi][nj][rh * 2],
                                                       s[mi][nj][rh * 2 + 1]);
                        pfr[mi][half2 * 2 + rh] = *(uint32_t*)&hp;
                    }
                }
            uint32_t bvh[8][2], bvl[8][2];
#pragma unroll
            for (int p = 0; p < 4; p++) {
                uint32_t krow = kb * 16 + ((lane >> 3) & 1) * 8 + r8;
                uint32_t nbyte = (2 * p + (lane >> 4)) * 16;
                uint32_t off = SWZ(krow * 128 + nbyte);
                uint32_t th[4], tl[4];
                ldm_x4t(th, kb_ + 8192 + off);
                ldm_x4t(tl, kb_ + 16384 + off);
                bvh[2 * p][0] = th[0]; bvh[2 * p][1] = th[1];
                bvh[2 * p + 1][0] = th[2]; bvh[2 * p + 1][1] = th[3];
                bvl[2 * p][0] = tl[0]; bvl[2 * p][1] = tl[1];
                bvl[2 * p + 1][0] = tl[2]; bvl[2 * p + 1][1] = tl[3];
            }
#pragma unroll
            for (int mi = 0; mi < 2; mi++)
#pragma unroll
                for (int nj = 0; nj < 8; nj++) {
                    mma_f16(o[mi][nj], pfr[mi], bvh[nj]);
                    mma_f16(o[mi][nj], pfr[mi], bvl[nj]);
                }
        }
        __syncthreads();
    }

    // ---- epilogue ----
    float inv[4];
#pragma unroll
    for (int i = 0; i < 4; i++) inv[i] = 1.f / lrow[i];
    float* ob = g_o + ((size_t)(l * MT_ + b * T_ + t0)) * D_ + h * HD_;
#pragma unroll
    for (int mi = 0; mi < 2; mi++)
#pragma unroll
        for (int half = 0; half < 2; half++) {
            int row = wid * 32 + mi * 16 + (lane >> 2) + half * 8;
            float iv = inv[mi * 2 + half];
            float* op = ob + (size_t)row * D_ + (lane & 3) * 2;
#pragma unroll
            for (int nj = 0; nj < 8; nj++)
                *(float2*)(op + nj * 8) =
                    make_float2(o[mi][nj][half * 2] * iv, o[mi][nj][half * 2 + 1] * iv);
        }
}

// ---------------- combine -> bf16-split y ----------------
__device__ __forceinline__ float blk_sum(float v, float* sred) {
#pragma unroll
    for (int off = 16; off; off >>= 1) v += __shfl_xor_sync(0xffffffffu, v, off);
    int w = threadIdx.x >> 5;
    if ((threadIdx.x & 31) == 0) sred[w] = v;
    __syncthreads();
    if (threadIdx.x < 32) {
        float t = (threadIdx.x < 8) ? sred[threadIdx.x] : 0.f;
#pragma unroll
        for (int off = 4; off; off >>= 1) t += __shfl_xor_sync(0xffffffffu, t, off);
        if (threadIdx.x == 0) sred[8] = t;
    }
    __syncthreads();
    return sred[8];
}

__global__ __launch_bounds__(256) void combine_kernel(
    const float* __restrict__ x, const float* __restrict__ ln_w,
    const float* __restrict__ final_ln_w, const float* __restrict__ alpha) {
    __shared__ float sred[9];
    const int row = blockIdx.x;
    const int d = threadIdx.x * 4;
    float4 a[NL_];
    float rl[NL_];
#pragma unroll
    for (int l2 = 0; l2 < NL_; l2++)
        a[l2] = *(const float4*)(g_o + ((size_t)l2 * MT_ + row) * D_ + d);
#pragma unroll
    for (int l2 = 0; l2 < NL_; l2++) {
        float s = a[l2].x * a[l2].x + a[l2].y * a[l2].y +
                  a[l2].z * a[l2].z + a[l2].w * a[l2].w;
        float tot = blk_sum(s, sred);
        rl[l2] = rsqrtf(tot * (1.f / D_) + EPS_) * g_lw[l2];
    }
    float4 xv = *(const float4*)(x + (size_t)row * D_ + d);
    float al = alpha[0];
    float4 acc = make_float4(al * xv.x, al * xv.y, al * xv.z, al * xv.w);
#pragma unroll
    for (int l2 = 0; l2 < NL_; l2++) {
        float4 w = *(const float4*)(ln_w + l2 * D_ + d);
        acc.x += a[l2].x * rl[l2] * w.x;
        acc.y += a[l2].y * rl[l2] * w.y;
        acc.z += a[l2].z * rl[l2] * w.z;
        acc.w += a[l2].w * rl[l2] * w.w;
    }
    float s2 = acc.x * acc.x + acc.y * acc.y + acc.z * acc.z + acc.w * acc.w;
    float rf = rsqrtf(blk_sum(s2, sred) * (1.f / D_) + EPS_);
    float4 fw = *(const float4*)(final_ln_w + d);
    float outv[4] = {acc.x * rf * fw.x, acc.y * rf * fw.y,
                     acc.z * rf * fw.z, acc.w * rf * fw.w};
    size_t base = (size_t)row * D_ + d;
#pragma unroll
    for (int j = 0; j < 4; j++) {
        __nv_bfloat16 h = __float2bfloat16(outv[j]);
        g_yhi[base + j] = h;
        g_ylo[base + j] = __float2bfloat16(outv[j] - __bfloat162float(h));
    }
}

// ---------------- launch ----------------
extern "C" void kernel_launch(void* const* d_in, const int* in_sizes, int n_in,
                              void* d_out, int out_size) {
    const float* x          = (const float*)d_in[0];
    const float* cosT       = (const float*)d_in[1];
    const float* sinT       = (const float*)d_in[2];
    const float* q_w        = (const float*)d_in[3];
    const float* k_w        = (const float*)d_in[4];
    const float* v_w        = (const float*)d_in[5];
    const float* ln_w       = (const float*)d_in[6];
    const float* lam        = (const float*)d_in[7];
    const float* out_w      = (const float*)d_in[8];
    const float* final_ln_w = (const float*)d_in[9];
    const float* alpha      = (const float*)d_in[10];

    __nv_bfloat16 *p_xhi, *p_xlo, *p_wqh, *p_wql, *p_woh, *p_wol, *p_yh, *p_yl;
    float* p_qkv;
    cudaGetSymbolAddress((void**)&p_xhi, g_xhi);
    cudaGetSymbolAddress((void**)&p_xlo, g_xlo);
    cudaGetSymbolAddress((void**)&p_wqh, g_wqkv_hi);
    cudaGetSymbolAddress((void**)&p_wql, g_wqkv_lo);
    cudaGetSymbolAddress((void**)&p_woh, g_wo_hi);
    cudaGetSymbolAddress((void**)&p_wol, g_wo_lo);
    cudaGetSymbolAddress((void**)&p_yh, g_yhi);
    cudaGetSymbolAddress((void**)&p_yl, g_ylo);
    cudaGetSymbolAddress((void**)&p_qkv, g_qkv);

    cudaFuncSetAttribute(gemm_tc, cudaFuncAttributeMaxDynamicSharedMemorySize, GSMEM);
    cudaFuncSetAttribute(attn_tc, cudaFuncAttributeMaxDynamicSharedMemorySize, ASMEM);

    k_prep<<<1, 32>>>(lam);
    split_f32_v4<<<(MT_ * D_) / 1024, 256>>>(x, p_xhi, p_xlo);
    pack_wqkv_v4<<<(NL_ * QKVW_ * D_) / 1024, 256>>>(q_w, k_w, v_w);
    split_f32_v4<<<(D_ * D_) / 1024, 256>>>(out_w, p_woh, p_wol);

    gemm_tc<<<dim3(16, 16, 3), 256, GSMEM>>>(p_xhi, p_xlo, p_wqh, p_wql,
                                             p_qkv, QKVW_, QKVW_,
                                             (long)MT_ * QKVW_);

    rope_q_kernel<<<(NL_ * MT_ * H_ * 32) / 256, 256>>>(cosT, sinT);
    rope_kv_kernel<<<(NL_ * MT_ * HKV_ * 32) / 256, 256>>>(cosT, sinT);
    attn_tc<<<dim3(32, 24), 128, ASMEM>>>();
    combine_kernel<<<MT_, 256>>>(x, ln_w, final_ln_w, alpha);

    gemm_tc<<<dim3(8, 16, 1), 256, GSMEM>>>(p_yh, p_yl, p_woh, p_wol,
                                            (float*)d_out, D_, D_, 0L);
}